// round 6
// baseline (speedup 1.0000x reference)
#include <cuda_runtime.h>
#include <cuda_fp16.h>
#include <cstdint>

// Problem constants
#define BATCH 8
#define FIN   64
#define NPTS  4096
#define FOUT  64
#define KNN   20

#define FULLMASK 0xffffffffu
#define BIGF 3.0e38f

// ---------------------------------------------------------------------------
// Device scratch (no allocations allowed)
// ---------------------------------------------------------------------------
__device__ float g_Yt[BATCH * NPTS * FOUT];                    // W2 . x_n
__device__ float g_Ct[BATCH * NPTS * FOUT];                    // (W1-W2).x_n + b
__device__ __align__(16) float g_sq[BATCH * NPTS];             // ||x_n||^2
__device__ int   g_idx[BATCH * NPTS * KNN];                    // knn indices
__device__ __align__(16) __half g_p[BATCH * NPTS * 128];       // [hi(64)|lo(64)]

// ---------------------------------------------------------------------------
// Portable PTX helpers (compile fine for compute_103)
// ---------------------------------------------------------------------------
__device__ __forceinline__ uint32_t smem_u32(const void* p) {
    uint32_t a;
    asm("{ .reg .u64 t; cvta.to.shared.u64 t, %1; cvt.u32.u64 %0, t; }" : "=r"(a) : "l"(p));
    return a;
}
__device__ __forceinline__ void ldsm_x4(uint32_t addr, uint32_t* r) {
    asm volatile("ldmatrix.sync.aligned.m8n8.x4.shared.b16 {%0,%1,%2,%3}, [%4];"
        : "=r"(r[0]), "=r"(r[1]), "=r"(r[2]), "=r"(r[3]) : "r"(addr));
}
__device__ __forceinline__ void mma16816(float* c, const uint32_t* a, const uint32_t* b) {
    asm volatile("mma.sync.aligned.m16n8k16.row.col.f32.f16.f16.f32 "
        "{%0,%1,%2,%3}, {%4,%5,%6,%7}, {%8,%9}, {%0,%1,%2,%3};"
        : "+f"(c[0]), "+f"(c[1]), "+f"(c[2]), "+f"(c[3])
        : "r"(a[0]), "r"(a[1]), "r"(a[2]), "r"(a[3]), "r"(b[0]), "r"(b[1]));
}
__device__ __forceinline__ unsigned long long pack2(float lo, float hi) {
    unsigned long long r;
    asm("mov.b64 %0, {%1, %2};" : "=l"(r) : "f"(lo), "f"(hi));
    return r;
}
__device__ __forceinline__ void unpack2(unsigned long long v, float& lo, float& hi) {
    asm("mov.b64 {%0, %1}, %2;" : "=f"(lo), "=f"(hi) : "l"(v));
}
__device__ __forceinline__ void fma2(unsigned long long& c, unsigned long long a,
                                     unsigned long long b) {
    asm("fma.rn.f32x2 %0, %1, %2, %0;" : "+l"(c) : "l"(a), "l"(b));
}
#define CP_ASYNC16(dst, src) \
    asm volatile("cp.async.cg.shared.global [%0], [%1], 16;" :: "r"(dst), "l"(src))
#define CP_COMMIT() asm volatile("cp.async.commit_group;" ::: "memory")
#define CP_WAIT1()  asm volatile("cp.async.wait_group 1;" ::: "memory")
#define CP_WAIT0()  asm volatile("cp.async.wait_group 0;" ::: "memory")
#define BAR_SYNC(id, cnt) \
    asm volatile("bar.sync %0, %1;" :: "r"(id), "r"(cnt) : "memory")
#define BAR_ARRIVE(id, cnt) \
    asm volatile("bar.arrive %0, %1;" :: "r"(id), "r"(cnt) : "memory")

// named barrier ids
#define NB_FULL0 1
#define NB_FULL1 2
#define NB_FREE0 3
#define NB_FREE1 4
#define NB_BGRP  5

// ---------------------------------------------------------------------------
// Kernel 1: per-point features Yt/Ct (f32x2 packed fma), sq norms, fp16 hi/lo
// grid (32, 8, 2): z selects output half (and pack limb) for occupancy
// ---------------------------------------------------------------------------
__global__ __launch_bounds__(128) void k1_features(
    const float* __restrict__ x, const float* __restrict__ W,
    const float* __restrict__ bvec)
{
    __shared__ float W2s[64][32];
    __shared__ float Wds[64][32];
    __shared__ float bs[32];

    const int bb   = blockIdx.y;
    const int n0   = blockIdx.x * 128;
    const int half = blockIdx.z;
    const int tid  = threadIdx.x;

    for (int idx = tid; idx < 64 * 32; idx += 128) {
        int f = idx >> 5, o = idx & 31;
        int og = half * 32 + o;
        float w1 = W[og * 128 + f];
        float w2 = W[og * 128 + 64 + f];
        W2s[f][o] = w2;
        Wds[f][o] = w1 - w2;
    }
    if (tid < 32) bs[tid] = bvec[half * 32 + tid];
    __syncthreads();

    const float* xb = x + (size_t)bb * FIN * NPTS;
    const int n = n0 + tid;

    float xr[64];
#pragma unroll
    for (int f = 0; f < 64; ++f) xr[f] = xb[f * NPTS + n];

    uint4* pdst = (uint4*)(g_p + ((size_t)(bb * NPTS + n)) * 128);
    if (half == 0) {
        float sq = 0.f;
#pragma unroll
        for (int f = 0; f < 64; ++f) sq = fmaf(xr[f], xr[f], sq);
        g_sq[bb * NPTS + n] = sq;
        // hi pack
#pragma unroll
        for (int q = 0; q < 8; ++q) {
            __half2 h[4];
#pragma unroll
            for (int e = 0; e < 4; ++e)
                h[e] = __floats2half2_rn(xr[q * 8 + 2 * e], xr[q * 8 + 2 * e + 1]);
            pdst[q] = make_uint4(*(unsigned*)&h[0], *(unsigned*)&h[1],
                                 *(unsigned*)&h[2], *(unsigned*)&h[3]);
        }
    } else {
        // lo pack
#pragma unroll
        for (int q = 0; q < 8; ++q) {
            float r[8];
#pragma unroll
            for (int e = 0; e < 8; ++e) {
                float xf = xr[q * 8 + e];
                r[e] = xf - __half2float(__float2half_rn(xf));
            }
            __half2 h[4];
#pragma unroll
            for (int e = 0; e < 4; ++e)
                h[e] = __floats2half2_rn(r[2 * e], r[2 * e + 1]);
            pdst[8 + q] = make_uint4(*(unsigned*)&h[0], *(unsigned*)&h[1],
                                     *(unsigned*)&h[2], *(unsigned*)&h[3]);
        }
    }

    const size_t base = ((size_t)(bb * NPTS + n)) * 64 + half * 32;

    unsigned long long ya2[16], ca2[16];
#pragma unroll
    for (int p = 0; p < 16; ++p) {
        ya2[p] = pack2(0.f, 0.f);
        ca2[p] = pack2(bs[2 * p], bs[2 * p + 1]);
    }

#pragma unroll 4
    for (int f = 0; f < 64; ++f) {
        const unsigned long long a2 = pack2(xr[f], xr[f]);
#pragma unroll
        for (int oo = 0; oo < 32; oo += 4) {
            float4 w2 = *(const float4*)&W2s[f][oo];
            float4 wd = *(const float4*)&Wds[f][oo];
            fma2(ya2[oo / 2],     a2, pack2(w2.x, w2.y));
            fma2(ya2[oo / 2 + 1], a2, pack2(w2.z, w2.w));
            fma2(ca2[oo / 2],     a2, pack2(wd.x, wd.y));
            fma2(ca2[oo / 2 + 1], a2, pack2(wd.z, wd.w));
        }
    }
    float4* Yp = (float4*)(g_Yt + base);
    float4* Cp = (float4*)(g_Ct + base);
#pragma unroll
    for (int q = 0; q < 8; ++q) {
        float y0, y1, y2, y3, c0, c1, c2, c3;
        unpack2(ya2[2 * q], y0, y1);
        unpack2(ya2[2 * q + 1], y2, y3);
        unpack2(ca2[2 * q], c0, c1);
        unpack2(ca2[2 * q + 1], c2, c3);
        Yp[q] = make_float4(y0, y1, y2, y3);
        Cp[q] = make_float4(c0, c1, c2, c3);
    }
}

// ---------------------------------------------------------------------------
// Kernel 2: WARP-SPECIALIZED HMMA distance GEMM + top-20
// 128 CTAs (8 batches x 16 row-blocks of 256), 512 threads.
// Warps 0-7: GEMM producers (32x32 warp tile, fp16 3-pass split).
// Warps 8-15: selection consumers (32 rows each, shuffle-shift top-20).
// Ds double-buffered, handoff via named-barrier arrive/sync pairs.
// ---------------------------------------------------------------------------
#define ROWS 256
#define TNC  32
#define NT   (NPTS / TNC)            // 128 tiles
#define DSS  33                      // Ds row stride (floats)

// smem byte offsets
#define SM_A   0                     // Ah[256][64] 32KB + Al 32KB
#define SM_B   65536                 // 2 bufs x (Bh 4KB + Bl 4KB) = 16KB
#define SM_SQ  81920                 // 4096 floats = 16KB
#define SM_D   98304                 // 2 bufs x 256 x 33 floats = 67584B
#define SM_TOT (SM_D + 2 * ROWS * DSS * 4)   // 165888

__global__ __launch_bounds__(512, 1) void k2_knn(void)
{
    extern __shared__ char sm[];
    const uint32_t smem_base = smem_u32(sm);
    float* Ds  = (float*)(sm + SM_D);
    const float* sqs = (const float*)(sm + SM_SQ);

    const int tid  = threadIdx.x;
    const int wid  = tid >> 5;
    const int lane = tid & 31;

    const int bb = blockIdx.x >> 4;
    const int n0 = (blockIdx.x & 15) * ROWS;

    const __half* gp = g_p + (size_t)bb * NPTS * 128;

    // ---- load A panels (hi|lo) swizzled: 256 rows x 16 chunks of 16B ----
    for (int idx = tid; idx < ROWS * 16; idx += 512) {
        int r = idx >> 4, ch = idx & 15;
        uint4 v = *(const uint4*)(gp + (size_t)(n0 + r) * 128 + ch * 8);
        uint32_t pan = (ch < 8) ? 0u : 32768u;
        uint32_t c16 = ch & 7;
        *(uint4*)(sm + SM_A + pan + r * 128 + ((c16 ^ (r & 7)) << 4)) = v;
    }
    // ---- load sq (whole batch) ----
    {
        const uint4* src = (const uint4*)(g_sq + (size_t)bb * NPTS);
        uint4* dst = (uint4*)(sm + SM_SQ);
        for (int i = tid; i < 1024; i += 512) dst[i] = src[i];
    }
    __syncthreads();

    if (wid < 8) {
        // ================= GEMM producers =================
        const int wg = wid;          // row group: rows wg*32 .. +32

        auto loadB = [&](int t, int buf) {
            const __half* src0 = gp + (size_t)t * TNC * 128;
            uint32_t dst0 = smem_base + SM_B + buf * 8192;
#pragma unroll
            for (int k = 0; k < 2; ++k) {
                int idx = tid + k * 256;          // 0..511 (tid<256 here)
                int r = idx >> 4, ch = idx & 15;
                uint32_t pan = (ch < 8) ? 0u : 4096u;
                uint32_t c16 = ch & 7;
                CP_ASYNC16(dst0 + pan + r * 128 + ((c16 ^ (r & 7)) << 4),
                           src0 + (size_t)r * 128 + ch * 8);
            }
        };

        loadB(0, 0);
        CP_COMMIT();

#pragma unroll 1
        for (int t = 0; t < NT; ++t) {
            const int buf = t & 1;
            if (t + 1 < NT) { loadB(t + 1, (t + 1) & 1); CP_COMMIT(); CP_WAIT1(); }
            else            { CP_WAIT0(); }
            BAR_SYNC(NB_BGRP, 256);              // B[t] visible to GEMM warps

            // ---- GEMM: 3 passes share fragments, ks-outer ----
            float acc[2][4][4];
#pragma unroll
            for (int mt = 0; mt < 2; ++mt)
#pragma unroll
                for (int nt = 0; nt < 4; ++nt)
#pragma unroll
                    for (int e = 0; e < 4; ++e) acc[mt][nt][e] = 0.f;

            const uint32_t abase = smem_base + SM_A;
            const uint32_t bbase = smem_base + SM_B + buf * 8192;
#pragma unroll
            for (int ks = 0; ks < 4; ++ks) {
                uint32_t ah[2][4], al[2][4], bh[2][4], bl[2][4];
                const int acha = ks * 2 + (lane >> 4);
                const int bcha = ks * 2 + ((lane >> 3) & 1);
#pragma unroll
                for (int mt = 0; mt < 2; ++mt) {
                    int row = wg * 32 + mt * 16 + (lane & 15);
                    uint32_t off = row * 128 + ((acha ^ (row & 7)) << 4);
                    ldsm_x4(abase + off, ah[mt]);
                    ldsm_x4(abase + 32768u + off, al[mt]);
                }
#pragma unroll
                for (int g = 0; g < 2; ++g) {
                    int row = g * 16 + (lane & 7) + ((lane >> 4) << 3);
                    uint32_t off = row * 128 + ((bcha ^ (row & 7)) << 4);
                    ldsm_x4(bbase + off, bh[g]);
                    ldsm_x4(bbase + 4096u + off, bl[g]);
                }
#pragma unroll
                for (int mt = 0; mt < 2; ++mt)
#pragma unroll
                    for (int nt = 0; nt < 4; ++nt)
                        mma16816(acc[mt][nt], ah[mt], &bh[nt >> 1][(nt & 1) * 2]);
#pragma unroll
                for (int mt = 0; mt < 2; ++mt)
#pragma unroll
                    for (int nt = 0; nt < 4; ++nt)
                        mma16816(acc[mt][nt], al[mt], &bh[nt >> 1][(nt & 1) * 2]);
#pragma unroll
                for (int mt = 0; mt < 2; ++mt)
#pragma unroll
                    for (int nt = 0; nt < 4; ++nt)
                        mma16816(acc[mt][nt], ah[mt], &bl[nt >> 1][(nt & 1) * 2]);
            }

            // ---- wait Ds[buf] free (scan of t-2 done), then stage ----
            if (t >= 2) BAR_SYNC(NB_FREE0 + buf, 512);
            float* db = Ds + buf * (ROWS * DSS);
#pragma unroll
            for (int mt = 0; mt < 2; ++mt) {
                int row0 = wg * 32 + mt * 16 + (lane >> 2);
#pragma unroll
                for (int nt = 0; nt < 4; ++nt) {
                    int col0 = nt * 8 + 2 * (lane & 3);
                    db[row0 * DSS + col0]           = acc[mt][nt][0];
                    db[row0 * DSS + col0 + 1]       = acc[mt][nt][1];
                    db[(row0 + 8) * DSS + col0]     = acc[mt][nt][2];
                    db[(row0 + 8) * DSS + col0 + 1] = acc[mt][nt][3];
                }
            }
            BAR_ARRIVE(NB_FULL0 + buf, 512);
        }
    } else {
        // ================= selection consumers =================
        const int sw = wid - 8;
        const int rowbase = sw * 32;

        float lv[32];
        int   li[32];
#pragma unroll
        for (int r = 0; r < 32; ++r) { lv[r] = BIGF; li[r] = 0; }

#pragma unroll 1
        for (int t = 0; t < NT; ++t) {
            const int buf = t & 1;
            BAR_SYNC(NB_FULL0 + buf, 512);       // Ds[buf] staged
            const float* db = Ds + buf * (ROWS * DSS);
            const float sqv = sqs[t * TNC + lane];
            const int   mcand = t * TNC + lane;  // this lane's candidate id

#pragma unroll
            for (int r = 0; r < 32; ++r) {
                const int row   = rowbase + r;
                const int nrowr = n0 + row;
                float k = fmaf(-2.0f, db[row * DSS + lane], sqv);
                if (mcand == nrowr) k = BIGF;    // self-exclusion

                float w = __shfl_sync(FULLMASK, lv[r], 19);
                unsigned b = __ballot_sync(FULLMASK, k < w);
                while (b) {
                    const int s = __ffs(b) - 1;
                    b &= b - 1;
                    const float key = __shfl_sync(FULLMASK, k, s);
                    if (key < w) {
                        // shuffle-shift sorted insert (ascending, lane19 worst)
                        const float vprev = __shfl_up_sync(FULLMASK, lv[r], 1);
                        const int   iprev = __shfl_up_sync(FULLMASK, li[r], 1);
                        const bool pv    = lv[r] > key;
                        const bool pprev = (lane == 0) ? false : (vprev > key);
                        lv[r] = pv ? (pprev ? vprev : key) : lv[r];
                        li[r] = pv ? (pprev ? iprev : (t * TNC + s)) : li[r];
                        w = __shfl_sync(FULLMASK, lv[r], 19);
                    }
                }
            }
            BAR_ARRIVE(NB_FREE0 + buf, 512);
        }

        // ---- write neighbor indices ----
#pragma unroll
        for (int r = 0; r < 32; ++r) {
            if (lane < KNN)
                g_idx[((size_t)(bb * NPTS + n0 + rowbase + r)) * KNN + lane] = li[r];
        }
    }
}

// ---------------------------------------------------------------------------
// Kernel 3: gather-max epilogue + transpose to [b][o][n]
// ---------------------------------------------------------------------------
__global__ __launch_bounds__(256) void k3_epilogue(float* __restrict__ out)
{
    __shared__ float outs[64][65];
    const int bb  = blockIdx.y;
    const int n0  = blockIdx.x * 64;
    const int tid = threadIdx.x;
    const int w    = tid >> 5;
    const int lane = tid & 31;

    const float* Y = g_Yt + (size_t)bb * NPTS * 64;
    const float* C = g_Ct + (size_t)bb * NPTS * 64;

#pragma unroll 1
    for (int s = 0; s < 8; ++s) {
        int nn = w * 8 + s;
        int n  = n0 + nn;
        int jj = 0;
        if (lane < KNN) jj = g_idx[((size_t)(bb * NPTS + n)) * KNN + lane];
        float m0v = -3.0e38f, m1v = -3.0e38f;
#pragma unroll
        for (int i = 0; i < KNN; ++i) {
            int j = __shfl_sync(0xffffffffu, jj, i);
            const float* yr = Y + (size_t)j * 64;
            m0v = fmaxf(m0v, yr[lane]);
            m1v = fmaxf(m1v, yr[lane + 32]);
        }
        outs[nn][lane]      = m0v + C[(size_t)n * 64 + lane];
        outs[nn][lane + 32] = m1v + C[(size_t)n * 64 + lane + 32];
    }
    __syncthreads();

    float* ob = out + (size_t)bb * FOUT * NPTS;
#pragma unroll
    for (int it = 0; it < 16; ++it) {
        int lin = it * 256 + tid;
        int o  = lin >> 6;
        int nn = lin & 63;
        ob[o * NPTS + n0 + nn] = outs[nn][o];
    }
}

// ---------------------------------------------------------------------------
extern "C" void kernel_launch(void* const* d_in, const int* in_sizes, int n_in,
                              void* d_out, int out_size)
{
    const float* x    = (const float*)d_in[0];
    const float* W    = (const float*)d_in[1];
    const float* bvec = (const float*)d_in[2];
    float* out        = (float*)d_out;

    cudaFuncSetAttribute(k2_knn, cudaFuncAttributeMaxDynamicSharedMemorySize, SM_TOT);

    k1_features<<<dim3(NPTS / 128, BATCH, 2), 128>>>(x, W, bvec);
    k2_knn<<<BATCH * (NPTS / ROWS), 512, SM_TOT>>>();
    k3_epilogue<<<dim3(NPTS / 64, BATCH), 256>>>(out);
}

// round 7
// speedup vs baseline: 1.3338x; 1.3338x over previous
#include <cuda_runtime.h>
#include <cuda_fp16.h>
#include <cstdint>

// Problem constants
#define BATCH 8
#define FIN   64
#define NPTS  4096
#define FOUT  64
#define KNN   20
#define KSEL  28                     // stage-1 list size (slack over KNN)

#define FULLMASK 0xffffffffu
#define BIGF 3.0e38f

// ---------------------------------------------------------------------------
// Device scratch (no allocations allowed)
// ---------------------------------------------------------------------------
__device__ float g_Yt[BATCH * NPTS * FOUT];                    // W2 . x_n
__device__ float g_Ct[BATCH * NPTS * FOUT];                    // (W1-W2).x_n + b
__device__ __align__(16) float g_sq[BATCH * NPTS];             // ||x_n||^2
__device__ int   g_idx[BATCH * NPTS * KNN];                    // knn indices
__device__ __align__(16) __half g_p[BATCH * NPTS * 128];       // [hi(64)|lo(64)]

// ---------------------------------------------------------------------------
// Portable PTX helpers (compile fine for compute_103)
// ---------------------------------------------------------------------------
__device__ __forceinline__ uint32_t smem_u32(const void* p) {
    uint32_t a;
    asm("{ .reg .u64 t; cvta.to.shared.u64 t, %1; cvt.u32.u64 %0, t; }" : "=r"(a) : "l"(p));
    return a;
}
__device__ __forceinline__ void ldsm_x4(uint32_t addr, uint32_t* r) {
    asm volatile("ldmatrix.sync.aligned.m8n8.x4.shared.b16 {%0,%1,%2,%3}, [%4];"
        : "=r"(r[0]), "=r"(r[1]), "=r"(r[2]), "=r"(r[3]) : "r"(addr));
}
__device__ __forceinline__ void mma16816(float* c, const uint32_t* a, const uint32_t* b) {
    asm volatile("mma.sync.aligned.m16n8k16.row.col.f32.f16.f16.f32 "
        "{%0,%1,%2,%3}, {%4,%5,%6,%7}, {%8,%9}, {%0,%1,%2,%3};"
        : "+f"(c[0]), "+f"(c[1]), "+f"(c[2]), "+f"(c[3])
        : "r"(a[0]), "r"(a[1]), "r"(a[2]), "r"(a[3]), "r"(b[0]), "r"(b[1]));
}
__device__ __forceinline__ unsigned long long pack2(float lo, float hi) {
    unsigned long long r;
    asm("mov.b64 %0, {%1, %2};" : "=l"(r) : "f"(lo), "f"(hi));
    return r;
}
__device__ __forceinline__ void unpack2(unsigned long long v, float& lo, float& hi) {
    asm("mov.b64 {%0, %1}, %2;" : "=f"(lo), "=f"(hi) : "l"(v));
}
__device__ __forceinline__ void fma2(unsigned long long& c, unsigned long long a,
                                     unsigned long long b) {
    asm("fma.rn.f32x2 %0, %1, %2, %0;" : "+l"(c) : "l"(a), "l"(b));
}
__device__ __forceinline__ float2 h2pair(unsigned h, unsigned l) {
    float2 a = __half22float2(*reinterpret_cast<const __half2*>(&h));
    float2 b = __half22float2(*reinterpret_cast<const __half2*>(&l));
    return make_float2(a.x + b.x, a.y + b.y);
}
#define CP_ASYNC16(dst, src) \
    asm volatile("cp.async.cg.shared.global [%0], [%1], 16;" :: "r"(dst), "l"(src))
#define CP_COMMIT() asm volatile("cp.async.commit_group;" ::: "memory")
#define CP_WAIT1()  asm volatile("cp.async.wait_group 1;" ::: "memory")
#define CP_WAIT0()  asm volatile("cp.async.wait_group 0;" ::: "memory")

// ---------------------------------------------------------------------------
// Kernel 1: per-point features Yt/Ct (f32x2 packed fma), sq norms, fp16 hi/lo
// grid (32, 8, 2): z selects output half (and pack limb)
// ---------------------------------------------------------------------------
__global__ __launch_bounds__(128) void k1_features(
    const float* __restrict__ x, const float* __restrict__ W,
    const float* __restrict__ bvec)
{
    __shared__ float W2s[64][32];
    __shared__ float Wds[64][32];
    __shared__ float bs[32];

    const int bb   = blockIdx.y;
    const int n0   = blockIdx.x * 128;
    const int half = blockIdx.z;
    const int tid  = threadIdx.x;

    for (int idx = tid; idx < 64 * 32; idx += 128) {
        int f = idx >> 5, o = idx & 31;
        int og = half * 32 + o;
        float w1 = W[og * 128 + f];
        float w2 = W[og * 128 + 64 + f];
        W2s[f][o] = w2;
        Wds[f][o] = w1 - w2;
    }
    if (tid < 32) bs[tid] = bvec[half * 32 + tid];
    __syncthreads();

    const float* xb = x + (size_t)bb * FIN * NPTS;
    const int n = n0 + tid;

    float xr[64];
#pragma unroll
    for (int f = 0; f < 64; ++f) xr[f] = xb[f * NPTS + n];

    uint4* pdst = (uint4*)(g_p + ((size_t)(bb * NPTS + n)) * 128);
    if (half == 0) {
        float sq = 0.f;
#pragma unroll
        for (int f = 0; f < 64; ++f) sq = fmaf(xr[f], xr[f], sq);
        g_sq[bb * NPTS + n] = sq;
#pragma unroll
        for (int q = 0; q < 8; ++q) {
            __half2 h[4];
#pragma unroll
            for (int e = 0; e < 4; ++e)
                h[e] = __floats2half2_rn(xr[q * 8 + 2 * e], xr[q * 8 + 2 * e + 1]);
            pdst[q] = make_uint4(*(unsigned*)&h[0], *(unsigned*)&h[1],
                                 *(unsigned*)&h[2], *(unsigned*)&h[3]);
        }
    } else {
#pragma unroll
        for (int q = 0; q < 8; ++q) {
            float r[8];
#pragma unroll
            for (int e = 0; e < 8; ++e) {
                float xf = xr[q * 8 + e];
                r[e] = xf - __half2float(__float2half_rn(xf));
            }
            __half2 h[4];
#pragma unroll
            for (int e = 0; e < 4; ++e)
                h[e] = __floats2half2_rn(r[2 * e], r[2 * e + 1]);
            pdst[8 + q] = make_uint4(*(unsigned*)&h[0], *(unsigned*)&h[1],
                                     *(unsigned*)&h[2], *(unsigned*)&h[3]);
        }
    }

    const size_t base = ((size_t)(bb * NPTS + n)) * 64 + half * 32;

    unsigned long long ya2[16], ca2[16];
#pragma unroll
    for (int p = 0; p < 16; ++p) {
        ya2[p] = pack2(0.f, 0.f);
        ca2[p] = pack2(bs[2 * p], bs[2 * p + 1]);
    }

#pragma unroll 4
    for (int f = 0; f < 64; ++f) {
        const unsigned long long a2 = pack2(xr[f], xr[f]);
#pragma unroll
        for (int oo = 0; oo < 32; oo += 4) {
            float4 w2 = *(const float4*)&W2s[f][oo];
            float4 wd = *(const float4*)&Wds[f][oo];
            fma2(ya2[oo / 2],     a2, pack2(w2.x, w2.y));
            fma2(ya2[oo / 2 + 1], a2, pack2(w2.z, w2.w));
            fma2(ca2[oo / 2],     a2, pack2(wd.x, wd.y));
            fma2(ca2[oo / 2 + 1], a2, pack2(wd.z, wd.w));
        }
    }
    float4* Yp = (float4*)(g_Yt + base);
    float4* Cp = (float4*)(g_Ct + base);
#pragma unroll
    for (int q = 0; q < 8; ++q) {
        float y0, y1, y2, y3, c0, c1, c2, c3;
        unpack2(ya2[2 * q], y0, y1);
        unpack2(ya2[2 * q + 1], y2, y3);
        unpack2(ca2[2 * q], c0, c1);
        unpack2(ca2[2 * q + 1], c2, c3);
        Yp[q] = make_float4(y0, y1, y2, y3);
        Cp[q] = make_float4(c0, c1, c2, c3);
    }
}

// ---------------------------------------------------------------------------
// Kernel 2: 1-pass fp16-hi HMMA distance GEMM + top-28 approx + exact refine
// grid 256 (8 batches x 32 row-blocks of 128), 256 threads, 8 warps (4x2)
// ---------------------------------------------------------------------------
#define TNC 64                       // candidate cols per tile
#define NT  (NPTS / TNC)             // 64 tiles
#define DSS 66                       // Ds row stride (floats)

// smem byte offsets
#define SM_A   0                     // Ah[128][64] halves = 16KB
#define SM_B   16384                 // 2 bufs x 8KB (hi only)
#define SM_SQ  32768                 // 2 bufs x 64 floats = 512B
#define SM_D   33280                 // Ds 128 x 66 floats = 33792B
#define SM_TOT (SM_D + 128 * DSS * 4)   // 67072

__global__ __launch_bounds__(256, 2) void k2_knn(void)
{
    extern __shared__ char sm[];
    const uint32_t smem_base = smem_u32(sm);
    float* Ds = (float*)(sm + SM_D);

    const int tid  = threadIdx.x;
    const int wid  = tid >> 5;
    const int lane = tid & 31;
    const int wr   = wid & 3;        // warp row group (32 rows)
    const int wc   = wid >> 2;       // warp col group (32 cols)

    const int bb = blockIdx.x >> 5;
    const int n0 = (blockIdx.x & 31) * 128;

    const __half* gp = g_p + (size_t)bb * NPTS * 128;

    // ---- load A panel (hi only) swizzled: 128 rows x 8 chunks of 16B ----
    for (int idx = tid; idx < 1024; idx += 256) {
        int r = idx >> 3, ch = idx & 7;
        uint4 v = *(const uint4*)(gp + (size_t)(n0 + r) * 128 + ch * 8);
        *(uint4*)(sm + SM_A + r * 128 + ((ch ^ (r & 7)) << 4)) = v;
    }

    // ---- B tile loader (hi only, cp.async) ----
    auto loadB = [&](int t, int buf) {
        const __half* src0 = gp + (size_t)t * TNC * 128;
        uint32_t dst0 = smem_base + SM_B + buf * 8192;
#pragma unroll
        for (int k = 0; k < 2; ++k) {
            int idx = tid + k * 256;             // 0..511
            int r = idx >> 3, ch = idx & 7;
            CP_ASYNC16(dst0 + r * 128 + ((ch ^ (r & 7)) << 4),
                       src0 + (size_t)r * 128 + ch * 8);
        }
        if (tid < 16)
            CP_ASYNC16(smem_base + SM_SQ + buf * 256 + tid * 16,
                       g_sq + bb * NPTS + t * TNC + tid * 4);
    };

    // ---- selection state: warp owns 16 rows; top-28 across lanes 0..27 ----
    float lv[16];
    int   li[16];
#pragma unroll
    for (int r = 0; r < 16; ++r) { lv[r] = BIGF; li[r] = 0; }
    const int srow0 = wid * 16;

    loadB(0, 0);
    CP_COMMIT();

#pragma unroll 1
    for (int t = 0; t < NT; ++t) {
        const int cur = t & 1;
        if (t + 1 < NT) { loadB(t + 1, (t + 1) & 1); CP_COMMIT(); CP_WAIT1(); }
        else            { CP_WAIT0(); }
        __syncthreads();                 // tile t resident (and A on t==0)

        // ---- GEMM: single hi-pass, 4 k16 steps ----
        float acc[2][4][4];
#pragma unroll
        for (int mt = 0; mt < 2; ++mt)
#pragma unroll
            for (int nt = 0; nt < 4; ++nt)
#pragma unroll
                for (int e = 0; e < 4; ++e) acc[mt][nt][e] = 0.f;

        const uint32_t abase = smem_base + SM_A;
        const uint32_t bbase = smem_base + SM_B + cur * 8192;
#pragma unroll
        for (int ks = 0; ks < 4; ++ks) {
            uint32_t ah[2][4], bh[2][4];
            const int acha = ks * 2 + (lane >> 4);
            const int bcha = ks * 2 + ((lane >> 3) & 1);
#pragma unroll
            for (int mt = 0; mt < 2; ++mt) {
                int row = wr * 32 + mt * 16 + (lane & 15);
                ldsm_x4(abase + row * 128 + ((acha ^ (row & 7)) << 4), ah[mt]);
            }
#pragma unroll
            for (int g = 0; g < 2; ++g) {
                int row = wc * 32 + g * 16 + (lane & 7) + ((lane >> 4) << 3);
                ldsm_x4(bbase + row * 128 + ((bcha ^ (row & 7)) << 4), bh[g]);
            }
#pragma unroll
            for (int mt = 0; mt < 2; ++mt)
#pragma unroll
                for (int nt = 0; nt < 4; ++nt)
                    mma16816(acc[mt][nt], ah[mt], &bh[nt >> 1][(nt & 1) * 2]);
        }

        // ---- stage dot tile to smem (stride 66) ----
#pragma unroll
        for (int mt = 0; mt < 2; ++mt) {
            int row0 = wr * 32 + mt * 16 + (lane >> 2);
#pragma unroll
            for (int nt = 0; nt < 4; ++nt) {
                int col0 = wc * 32 + nt * 8 + 2 * (lane & 3);
                Ds[row0 * DSS + col0]           = acc[mt][nt][0];
                Ds[row0 * DSS + col0 + 1]       = acc[mt][nt][1];
                Ds[(row0 + 8) * DSS + col0]     = acc[mt][nt][2];
                Ds[(row0 + 8) * DSS + col0 + 1] = acc[mt][nt][3];
            }
        }
        __syncthreads();

        // ---- warp-cooperative top-28 (approx keys) ----
        const float2 sqv = ((const float2*)(sm + SM_SQ + cur * 256))[lane];
        const int m0g = t * TNC + 2 * lane;
        const int m1g = m0g + 1;

#pragma unroll
        for (int r = 0; r < 16; ++r) {
            const int row   = srow0 + r;
            const int nrowr = n0 + row;
            const float2 d2 = *(const float2*)&Ds[row * DSS + 2 * lane];
            float k0 = fmaf(-2.0f, d2.x, sqv.x);
            float k1 = fmaf(-2.0f, d2.y, sqv.y);
            if (m0g == nrowr) k0 = BIGF;          // self-exclusion
            if (m1g == nrowr) k1 = BIGF;

            float w = __shfl_sync(FULLMASK, lv[r], KSEL - 1);
            unsigned b = __ballot_sync(FULLMASK, fminf(k0, k1) < w);
            while (b) {
                const int s = __ffs(b) - 1;
                b &= b - 1;
                const float K0 = __shfl_sync(FULLMASK, k0, s);
                const float K1 = __shfl_sync(FULLMASK, k1, s);
                const int   mb = t * TNC + 2 * s;
#pragma unroll
                for (int e = 0; e < 2; ++e) {
                    const float key = e ? K1 : K0;
                    if (key < w) {
                        const float vprev = __shfl_up_sync(FULLMASK, lv[r], 1);
                        const int   iprev = __shfl_up_sync(FULLMASK, li[r], 1);
                        const bool pv    = lv[r] > key;
                        const bool pprev = (lane == 0) ? false : (vprev > key);
                        lv[r] = pv ? (pprev ? vprev : key) : lv[r];
                        li[r] = pv ? (pprev ? iprev : (mb + e)) : li[r];
                        w = __shfl_sync(FULLMASK, lv[r], KSEL - 1);
                    }
                }
            }
        }
        __syncthreads();                 // Ds / sq reusable
    }

    // ---- stage 2: exact refinement of the 28 survivors, pick exact top-20 ----
    const float* sqg = g_sq + (size_t)bb * NPTS;
#pragma unroll 1
    for (int r = 0; r < 16; ++r) {
        const int nrowg = n0 + srow0 + r;
        const unsigned* pn = (const unsigned*)(gp + (size_t)nrowg * 128);
        const float2 an = h2pair(pn[lane], pn[32 + lane]);   // own point, 2 elems/lane

        float mykey = BIGF;
#pragma unroll 1
        for (int c = 0; c < KSEL; ++c) {
            const int m = __shfl_sync(FULLMASK, li[r], c);
            const unsigned* pm = (const unsigned*)(gp + (size_t)m * 128);
            const float2 am = h2pair(pm[lane], pm[32 + lane]);
            float part = fmaf(an.x, am.x, an.y * am.y);
            part += __shfl_xor_sync(FULLMASK, part, 16);
            part += __shfl_xor_sync(FULLMASK, part, 8);
            part += __shfl_xor_sync(FULLMASK, part, 4);
            part += __shfl_xor_sync(FULLMASK, part, 2);
            part += __shfl_xor_sync(FULLMASK, part, 1);
            const float key = fmaf(-2.0f, part, sqg[m]);
            if (lane == c) mykey = key;
        }

        // exact top-20 select from the 28 exact keys
        float nv = BIGF; int ni = 0;
        float w = BIGF;
#pragma unroll 1
        for (int s = 0; s < KSEL; ++s) {
            const float K = __shfl_sync(FULLMASK, mykey, s);
            const int   M = __shfl_sync(FULLMASK, li[r], s);
            if (K < w) {
                const float vprev = __shfl_up_sync(FULLMASK, nv, 1);
                const int   iprev = __shfl_up_sync(FULLMASK, ni, 1);
                const bool pv    = nv > K;
                const bool pprev = (lane == 0) ? false : (vprev > K);
                nv = pv ? (pprev ? vprev : K) : nv;
                ni = pv ? (pprev ? iprev : M) : ni;
                w = __shfl_sync(FULLMASK, nv, KNN - 1);
            }
        }
        if (lane < KNN)
            g_idx[((size_t)(bb * NPTS + nrowg)) * KNN + lane] = ni;
    }
}

// ---------------------------------------------------------------------------
// Kernel 3: gather-max epilogue + transpose to [b][o][n]
// ---------------------------------------------------------------------------
__global__ __launch_bounds__(256) void k3_epilogue(float* __restrict__ out)
{
    __shared__ float outs[64][65];
    const int bb  = blockIdx.y;
    const int n0  = blockIdx.x * 64;
    const int tid = threadIdx.x;
    const int w    = tid >> 5;
    const int lane = tid & 31;

    const float* Y = g_Yt + (size_t)bb * NPTS * 64;
    const float* C = g_Ct + (size_t)bb * NPTS * 64;

#pragma unroll 1
    for (int s = 0; s < 8; ++s) {
        int nn = w * 8 + s;
        int n  = n0 + nn;
        int jj = 0;
        if (lane < KNN) jj = g_idx[((size_t)(bb * NPTS + n)) * KNN + lane];
        float m0v = -3.0e38f, m1v = -3.0e38f;
#pragma unroll
        for (int i = 0; i < KNN; ++i) {
            int j = __shfl_sync(0xffffffffu, jj, i);
            const float* yr = Y + (size_t)j * 64;
            m0v = fmaxf(m0v, yr[lane]);
            m1v = fmaxf(m1v, yr[lane + 32]);
        }
        outs[nn][lane]      = m0v + C[(size_t)n * 64 + lane];
        outs[nn][lane + 32] = m1v + C[(size_t)n * 64 + lane + 32];
    }
    __syncthreads();

    float* ob = out + (size_t)bb * FOUT * NPTS;
#pragma unroll
    for (int it = 0; it < 16; ++it) {
        int lin = it * 256 + tid;
        int o  = lin >> 6;
        int nn = lin & 63;
        ob[o * NPTS + n0 + nn] = outs[nn][o];
    }
}

// ---------------------------------------------------------------------------
extern "C" void kernel_launch(void* const* d_in, const int* in_sizes, int n_in,
                              void* d_out, int out_size)
{
    const float* x    = (const float*)d_in[0];
    const float* W    = (const float*)d_in[1];
    const float* bvec = (const float*)d_in[2];
    float* out        = (float*)d_out;

    cudaFuncSetAttribute(k2_knn, cudaFuncAttributeMaxDynamicSharedMemorySize, SM_TOT);

    k1_features<<<dim3(NPTS / 128, BATCH, 2), 128>>>(x, W, bvec);
    k2_knn<<<BATCH * (NPTS / 128), 256, SM_TOT>>>();
    k3_epilogue<<<dim3(NPTS / 64, BATCH), 256>>>(out);
}

// round 8
// speedup vs baseline: 1.4433x; 1.0821x over previous
#include <cuda_runtime.h>
#include <cuda_fp16.h>
#include <cstdint>

// Problem constants
#define BATCH 8
#define FIN   64
#define NPTS  4096
#define FOUT  64
#define KNN   20
#define KSEL  28                     // stage-1 list size (slack over KNN)

#define FULLMASK 0xffffffffu
#define BIGF 3.0e38f

// ---------------------------------------------------------------------------
// Device scratch (no allocations allowed)
// ---------------------------------------------------------------------------
__device__ float g_Yt[BATCH * NPTS * FOUT];                    // W2 . x_n
__device__ float g_Ct[BATCH * NPTS * FOUT];                    // (W1-W2).x_n + b
__device__ __align__(16) float g_sq[BATCH * NPTS];             // ||x_n||^2
__device__ int   g_idx[BATCH * NPTS * KNN];                    // knn indices
__device__ __align__(16) __half g_p[BATCH * NPTS * 128];       // [hi(64)|lo(64)]

// ---------------------------------------------------------------------------
// Portable PTX helpers (compile fine for compute_103)
// ---------------------------------------------------------------------------
__device__ __forceinline__ uint32_t smem_u32(const void* p) {
    uint32_t a;
    asm("{ .reg .u64 t; cvta.to.shared.u64 t, %1; cvt.u32.u64 %0, t; }" : "=r"(a) : "l"(p));
    return a;
}
__device__ __forceinline__ void ldsm_x4(uint32_t addr, uint32_t* r) {
    asm volatile("ldmatrix.sync.aligned.m8n8.x4.shared.b16 {%0,%1,%2,%3}, [%4];"
        : "=r"(r[0]), "=r"(r[1]), "=r"(r[2]), "=r"(r[3]) : "r"(addr));
}
__device__ __forceinline__ void mma16816(float* c, const uint32_t* a, const uint32_t* b) {
    asm volatile("mma.sync.aligned.m16n8k16.row.col.f32.f16.f16.f32 "
        "{%0,%1,%2,%3}, {%4,%5,%6,%7}, {%8,%9}, {%0,%1,%2,%3};"
        : "+f"(c[0]), "+f"(c[1]), "+f"(c[2]), "+f"(c[3])
        : "r"(a[0]), "r"(a[1]), "r"(a[2]), "r"(a[3]), "r"(b[0]), "r"(b[1]));
}
__device__ __forceinline__ unsigned long long pack2(float lo, float hi) {
    unsigned long long r;
    asm("mov.b64 %0, {%1, %2};" : "=l"(r) : "f"(lo), "f"(hi));
    return r;
}
__device__ __forceinline__ void unpack2(unsigned long long v, float& lo, float& hi) {
    asm("mov.b64 {%0, %1}, %2;" : "=f"(lo), "=f"(hi) : "l"(v));
}
__device__ __forceinline__ void fma2(unsigned long long& c, unsigned long long a,
                                     unsigned long long b) {
    asm("fma.rn.f32x2 %0, %1, %2, %0;" : "+l"(c) : "l"(a), "l"(b));
}
__device__ __forceinline__ float2 h2pair(unsigned h, unsigned l) {
    float2 a = __half22float2(*reinterpret_cast<const __half2*>(&h));
    float2 b = __half22float2(*reinterpret_cast<const __half2*>(&l));
    return make_float2(a.x + b.x, a.y + b.y);
}
#define CP_ASYNC16(dst, src) \
    asm volatile("cp.async.cg.shared.global [%0], [%1], 16;" :: "r"(dst), "l"(src))
#define CP_COMMIT() asm volatile("cp.async.commit_group;" ::: "memory")
#define CP_WAIT1()  asm volatile("cp.async.wait_group 1;" ::: "memory")
#define CP_WAIT0()  asm volatile("cp.async.wait_group 0;" ::: "memory")

// ---------------------------------------------------------------------------
// Kernel 1: per-point features Yt/Ct (f32x2 packed fma), sq norms, fp16 hi/lo
// ---------------------------------------------------------------------------
__global__ __launch_bounds__(128) void k1_features(
    const float* __restrict__ x, const float* __restrict__ W,
    const float* __restrict__ bvec)
{
    __shared__ float W2s[64][32];
    __shared__ float Wds[64][32];
    __shared__ float bs[32];

    const int bb   = blockIdx.y;
    const int n0   = blockIdx.x * 128;
    const int half = blockIdx.z;
    const int tid  = threadIdx.x;

    for (int idx = tid; idx < 64 * 32; idx += 128) {
        int f = idx >> 5, o = idx & 31;
        int og = half * 32 + o;
        float w1 = W[og * 128 + f];
        float w2 = W[og * 128 + 64 + f];
        W2s[f][o] = w2;
        Wds[f][o] = w1 - w2;
    }
    if (tid < 32) bs[tid] = bvec[half * 32 + tid];
    __syncthreads();

    const float* xb = x + (size_t)bb * FIN * NPTS;
    const int n = n0 + tid;

    float xr[64];
#pragma unroll
    for (int f = 0; f < 64; ++f) xr[f] = xb[f * NPTS + n];

    uint4* pdst = (uint4*)(g_p + ((size_t)(bb * NPTS + n)) * 128);
    if (half == 0) {
        float sq = 0.f;
#pragma unroll
        for (int f = 0; f < 64; ++f) sq = fmaf(xr[f], xr[f], sq);
        g_sq[bb * NPTS + n] = sq;
#pragma unroll
        for (int q = 0; q < 8; ++q) {
            __half2 h[4];
#pragma unroll
            for (int e = 0; e < 4; ++e)
                h[e] = __floats2half2_rn(xr[q * 8 + 2 * e], xr[q * 8 + 2 * e + 1]);
            pdst[q] = make_uint4(*(unsigned*)&h[0], *(unsigned*)&h[1],
                                 *(unsigned*)&h[2], *(unsigned*)&h[3]);
        }
    } else {
#pragma unroll
        for (int q = 0; q < 8; ++q) {
            float r[8];
#pragma unroll
            for (int e = 0; e < 8; ++e) {
                float xf = xr[q * 8 + e];
                r[e] = xf - __half2float(__float2half_rn(xf));
            }
            __half2 h[4];
#pragma unroll
            for (int e = 0; e < 4; ++e)
                h[e] = __floats2half2_rn(r[2 * e], r[2 * e + 1]);
            pdst[8 + q] = make_uint4(*(unsigned*)&h[0], *(unsigned*)&h[1],
                                     *(unsigned*)&h[2], *(unsigned*)&h[3]);
        }
    }

    const size_t base = ((size_t)(bb * NPTS + n)) * 64 + half * 32;

    unsigned long long ya2[16], ca2[16];
#pragma unroll
    for (int p = 0; p < 16; ++p) {
        ya2[p] = pack2(0.f, 0.f);
        ca2[p] = pack2(bs[2 * p], bs[2 * p + 1]);
    }

#pragma unroll 4
    for (int f = 0; f < 64; ++f) {
        const unsigned long long a2 = pack2(xr[f], xr[f]);
#pragma unroll
        for (int oo = 0; oo < 32; oo += 4) {
            float4 w2 = *(const float4*)&W2s[f][oo];
            float4 wd = *(const float4*)&Wds[f][oo];
            fma2(ya2[oo / 2],     a2, pack2(w2.x, w2.y));
            fma2(ya2[oo / 2 + 1], a2, pack2(w2.z, w2.w));
            fma2(ca2[oo / 2],     a2, pack2(wd.x, wd.y));
            fma2(ca2[oo / 2 + 1], a2, pack2(wd.z, wd.w));
        }
    }
    float4* Yp = (float4*)(g_Yt + base);
    float4* Cp = (float4*)(g_Ct + base);
#pragma unroll
    for (int q = 0; q < 8; ++q) {
        float y0, y1, y2, y3, c0, c1, c2, c3;
        unpack2(ya2[2 * q], y0, y1);
        unpack2(ya2[2 * q + 1], y2, y3);
        unpack2(ca2[2 * q], c0, c1);
        unpack2(ca2[2 * q + 1], c2, c3);
        Yp[q] = make_float4(y0, y1, y2, y3);
        Cp[q] = make_float4(c0, c1, c2, c3);
    }
}

// ---------------------------------------------------------------------------
// Kernel 2: 1-pass fp16-hi HMMA distance GEMM + top-28 approx + exact refine
// grid 256 (8 batches x 32 row-blocks of 128), 256 threads, 8 warps (4x2)
// Stage-2 loops are fully unrolled over owned rows -> NO register spills.
// ---------------------------------------------------------------------------
#define TNC 64                       // candidate cols per tile
#define NT  (NPTS / TNC)             // 64 tiles
#define DSS 66                       // Ds row stride (floats)

// smem byte offsets
#define SM_A   0                     // Ah[128][64] = 16KB
#define SM_B   16384                 // 2 bufs x 8KB (hi only)
#define SM_SQ  32768                 // 2 bufs x 64 floats = 512B
#define SM_D   33280                 // Ds 128 x 66 floats = 33792B
#define SM_TOT (SM_D + 128 * DSS * 4)   // 67072

__global__ __launch_bounds__(256, 2) void k2_knn(void)
{
    extern __shared__ char sm[];
    const uint32_t smem_base = smem_u32(sm);
    float* Ds = (float*)(sm + SM_D);

    const int tid  = threadIdx.x;
    const int wid  = tid >> 5;
    const int lane = tid & 31;
    const int wr   = wid & 3;        // warp row group (32 rows)
    const int wc   = wid >> 2;       // warp col group (32 cols)

    const int bb = blockIdx.x >> 5;
    const int n0 = (blockIdx.x & 31) * 128;

    const __half* gp = g_p + (size_t)bb * NPTS * 128;

    // ---- load A panel (hi only) swizzled: 128 rows x 8 chunks of 16B ----
    for (int idx = tid; idx < 1024; idx += 256) {
        int r = idx >> 3, ch = idx & 7;
        uint4 v = *(const uint4*)(gp + (size_t)(n0 + r) * 128 + ch * 8);
        *(uint4*)(sm + SM_A + r * 128 + ((ch ^ (r & 7)) << 4)) = v;
    }

    // ---- B tile loader (hi only, cp.async) ----
    auto loadB = [&](int t, int buf) {
        const __half* src0 = gp + (size_t)t * TNC * 128;
        uint32_t dst0 = smem_base + SM_B + buf * 8192;
#pragma unroll
        for (int k = 0; k < 2; ++k) {
            int idx = tid + k * 256;             // 0..511
            int r = idx >> 3, ch = idx & 7;
            CP_ASYNC16(dst0 + r * 128 + ((ch ^ (r & 7)) << 4),
                       src0 + (size_t)r * 128 + ch * 8);
        }
        if (tid < 16)
            CP_ASYNC16(smem_base + SM_SQ + buf * 256 + tid * 16,
                       g_sq + bb * NPTS + t * TNC + tid * 4);
    };

    // ---- selection state: warp owns 16 rows; top-28 across lanes 0..27 ----
    float lv[16];
    int   li[16];
#pragma unroll
    for (int r = 0; r < 16; ++r) { lv[r] = BIGF; li[r] = 0; }
    const int srow0 = wid * 16;

    loadB(0, 0);
    CP_COMMIT();

#pragma unroll 1
    for (int t = 0; t < NT; ++t) {
        const int cur = t & 1;
        if (t + 1 < NT) { loadB(t + 1, (t + 1) & 1); CP_COMMIT(); CP_WAIT1(); }
        else            { CP_WAIT0(); }
        __syncthreads();                 // tile t resident (and A on t==0)

        // ---- GEMM: single hi-pass, 4 k16 steps ----
        float acc[2][4][4];
#pragma unroll
        for (int mt = 0; mt < 2; ++mt)
#pragma unroll
            for (int nt = 0; nt < 4; ++nt)
#pragma unroll
                for (int e = 0; e < 4; ++e) acc[mt][nt][e] = 0.f;

        const uint32_t abase = smem_base + SM_A;
        const uint32_t bbase = smem_base + SM_B + cur * 8192;
#pragma unroll
        for (int ks = 0; ks < 4; ++ks) {
            uint32_t ah[2][4], bh[2][4];
            const int acha = ks * 2 + (lane >> 4);
            const int bcha = ks * 2 + ((lane >> 3) & 1);
#pragma unroll
            for (int mt = 0; mt < 2; ++mt) {
                int row = wr * 32 + mt * 16 + (lane & 15);
                ldsm_x4(abase + row * 128 + ((acha ^ (row & 7)) << 4), ah[mt]);
            }
#pragma unroll
            for (int g = 0; g < 2; ++g) {
                int row = wc * 32 + g * 16 + (lane & 7) + ((lane >> 4) << 3);
                ldsm_x4(bbase + row * 128 + ((bcha ^ (row & 7)) << 4), bh[g]);
            }
#pragma unroll
            for (int mt = 0; mt < 2; ++mt)
#pragma unroll
                for (int nt = 0; nt < 4; ++nt)
                    mma16816(acc[mt][nt], ah[mt], &bh[nt >> 1][(nt & 1) * 2]);
        }

        // ---- stage dot tile to smem (stride 66) ----
#pragma unroll
        for (int mt = 0; mt < 2; ++mt) {
            int row0 = wr * 32 + mt * 16 + (lane >> 2);
#pragma unroll
            for (int nt = 0; nt < 4; ++nt) {
                int col0 = wc * 32 + nt * 8 + 2 * (lane & 3);
                Ds[row0 * DSS + col0]           = acc[mt][nt][0];
                Ds[row0 * DSS + col0 + 1]       = acc[mt][nt][1];
                Ds[(row0 + 8) * DSS + col0]     = acc[mt][nt][2];
                Ds[(row0 + 8) * DSS + col0 + 1] = acc[mt][nt][3];
            }
        }
        __syncthreads();

        // ---- warp-cooperative top-28 (approx keys) ----
        const float2 sqv = ((const float2*)(sm + SM_SQ + cur * 256))[lane];
        const int m0g = t * TNC + 2 * lane;
        const int m1g = m0g + 1;

#pragma unroll
        for (int r = 0; r < 16; ++r) {
            const int row   = srow0 + r;
            const int nrowr = n0 + row;
            const float2 d2 = *(const float2*)&Ds[row * DSS + 2 * lane];
            float k0 = fmaf(-2.0f, d2.x, sqv.x);
            float k1 = fmaf(-2.0f, d2.y, sqv.y);
            if (m0g == nrowr) k0 = BIGF;          // self-exclusion
            if (m1g == nrowr) k1 = BIGF;

            float w = __shfl_sync(FULLMASK, lv[r], KSEL - 1);
            unsigned b = __ballot_sync(FULLMASK, fminf(k0, k1) < w);
            while (b) {
                const int s = __ffs(b) - 1;
                b &= b - 1;
                const float K0 = __shfl_sync(FULLMASK, k0, s);
                const float K1 = __shfl_sync(FULLMASK, k1, s);
                const int   mb = t * TNC + 2 * s;
#pragma unroll
                for (int e = 0; e < 2; ++e) {
                    const float key = e ? K1 : K0;
                    if (key < w) {
                        const float vprev = __shfl_up_sync(FULLMASK, lv[r], 1);
                        const int   iprev = __shfl_up_sync(FULLMASK, li[r], 1);
                        const bool pv    = lv[r] > key;
                        const bool pprev = (lane == 0) ? false : (vprev > key);
                        lv[r] = pv ? (pprev ? vprev : key) : lv[r];
                        li[r] = pv ? (pprev ? iprev : (mb + e)) : li[r];
                        w = __shfl_sync(FULLMASK, lv[r], KSEL - 1);
                    }
                }
            }
        }
        __syncthreads();                 // Ds / sq reusable
    }

    // ---- stage 2: exact refinement (fully unrolled over rows: no spills) ----
    const float* sqg = g_sq + (size_t)bb * NPTS;
#pragma unroll
    for (int r = 0; r < 16; ++r) {
        const int nrowg = n0 + srow0 + r;
        const unsigned* pn = (const unsigned*)(gp + (size_t)nrowg * 128);
        const float2 an = h2pair(pn[lane], pn[32 + lane]);   // own point, 2 elems/lane

        float mykey = BIGF;
#pragma unroll 1
        for (int c = 0; c < KSEL; c += 2) {
            const int mA = __shfl_sync(FULLMASK, li[r], c);
            const int mB = __shfl_sync(FULLMASK, li[r], c + 1);
            const unsigned* pA = (const unsigned*)(gp + (size_t)mA * 128);
            const unsigned* pB = (const unsigned*)(gp + (size_t)mB * 128);
            const unsigned a0 = pA[lane], a1 = pA[32 + lane];
            const unsigned b0 = pB[lane], b1 = pB[32 + lane];
            const float2 aA = h2pair(a0, a1);
            const float2 aB = h2pair(b0, b1);
            float pa = fmaf(an.x, aA.x, an.y * aA.y);
            float pb = fmaf(an.x, aB.x, an.y * aB.y);
#pragma unroll
            for (int s = 16; s >= 1; s >>= 1) {
                pa += __shfl_xor_sync(FULLMASK, pa, s);
                pb += __shfl_xor_sync(FULLMASK, pb, s);
            }
            const float keyA = fmaf(-2.0f, pa, sqg[mA]);
            const float keyB = fmaf(-2.0f, pb, sqg[mB]);
            if (lane == c)     mykey = keyA;
            if (lane == c + 1) mykey = keyB;
        }

        // exact top-20 select from the 28 exact keys
        float nv = BIGF; int ni = 0;
        float w = BIGF;
#pragma unroll 1
        for (int s = 0; s < KSEL; ++s) {
            const float K = __shfl_sync(FULLMASK, mykey, s);
            const int   M = __shfl_sync(FULLMASK, li[r], s);
            if (K < w) {
                const float vprev = __shfl_up_sync(FULLMASK, nv, 1);
                const int   iprev = __shfl_up_sync(FULLMASK, ni, 1);
                const bool pv    = nv > K;
                const bool pprev = (lane == 0) ? false : (vprev > K);
                nv = pv ? (pprev ? vprev : K) : nv;
                ni = pv ? (pprev ? iprev : M) : ni;
                w = __shfl_sync(FULLMASK, nv, KNN - 1);
            }
        }
        if (lane < KNN)
            g_idx[((size_t)(bb * NPTS + nrowg)) * KNN + lane] = ni;
    }
}

// ---------------------------------------------------------------------------
// Kernel 3: gather-max epilogue + transpose to [b][o][n]
// ---------------------------------------------------------------------------
__global__ __launch_bounds__(256) void k3_epilogue(float* __restrict__ out)
{
    __shared__ float outs[64][65];
    const int bb  = blockIdx.y;
    const int n0  = blockIdx.x * 64;
    const int tid = threadIdx.x;
    const int w    = tid >> 5;
    const int lane = tid & 31;

    const float* Y = g_Yt + (size_t)bb * NPTS * 64;
    const float* C = g_Ct + (size_t)bb * NPTS * 64;

#pragma unroll 1
    for (int s = 0; s < 8; ++s) {
        int nn = w * 8 + s;
        int n  = n0 + nn;
        int jj = 0;
        if (lane < KNN) jj = g_idx[((size_t)(bb * NPTS + n)) * KNN + lane];
        float m0v = -3.0e38f, m1v = -3.0e38f;
#pragma unroll
        for (int i = 0; i < KNN; ++i) {
            int j = __shfl_sync(0xffffffffu, jj, i);
            const float* yr = Y + (size_t)j * 64;
            m0v = fmaxf(m0v, yr[lane]);
            m1v = fmaxf(m1v, yr[lane + 32]);
        }
        outs[nn][lane]      = m0v + C[(size_t)n * 64 + lane];
        outs[nn][lane + 32] = m1v + C[(size_t)n * 64 + lane + 32];
    }
    __syncthreads();

    float* ob = out + (size_t)bb * FOUT * NPTS;
#pragma unroll
    for (int it = 0; it < 16; ++it) {
        int lin = it * 256 + tid;
        int o  = lin >> 6;
        int nn = lin & 63;
        ob[o * NPTS + n0 + nn] = outs[nn][o];
    }
}

// ---------------------------------------------------------------------------
extern "C" void kernel_launch(void* const* d_in, const int* in_sizes, int n_in,
                              void* d_out, int out_size)
{
    const float* x    = (const float*)d_in[0];
    const float* W    = (const float*)d_in[1];
    const float* bvec = (const float*)d_in[2];
    float* out        = (float*)d_out;

    cudaFuncSetAttribute(k2_knn, cudaFuncAttributeMaxDynamicSharedMemorySize, SM_TOT);

    k1_features<<<dim3(NPTS / 128, BATCH, 2), 128>>>(x, W, bvec);
    k2_knn<<<BATCH * (NPTS / 128), 256, SM_TOT>>>();
    k3_epilogue<<<dim3(NPTS / 64, BATCH), 256>>>(out);
}

// round 9
// speedup vs baseline: 1.5431x; 1.0692x over previous
#include <cuda_runtime.h>
#include <cuda_fp16.h>
#include <cstdint>

// Problem constants
#define BATCH 8
#define FIN   64
#define NPTS  4096
#define FOUT  64
#define KNN   20
#define KSEL  28                     // stage-1 list size (slack over KNN)

#define FULLMASK 0xffffffffu
#define BIGF 3.0e38f

// ---------------------------------------------------------------------------
// Device scratch (no allocations allowed)
// ---------------------------------------------------------------------------
__device__ float g_Yt[BATCH * NPTS * FOUT];                    // W2 . x_n
__device__ float g_Ct[BATCH * NPTS * FOUT];                    // (W1-W2).x_n + b
__device__ __align__(16) float g_sq[BATCH * NPTS];             // ||x_n||^2
__device__ int   g_idx[BATCH * NPTS * KNN];                    // refined knn indices
__device__ int   g_sel[BATCH * NPTS * KSEL];                   // stage-1 candidates
__device__ __align__(16) __half g_p[BATCH * NPTS * 128];       // [hi(64)|lo(64)]

// ---------------------------------------------------------------------------
// Portable PTX helpers (compile fine for compute_103)
// ---------------------------------------------------------------------------
__device__ __forceinline__ uint32_t smem_u32(const void* p) {
    uint32_t a;
    asm("{ .reg .u64 t; cvta.to.shared.u64 t, %1; cvt.u32.u64 %0, t; }" : "=r"(a) : "l"(p));
    return a;
}
__device__ __forceinline__ void ldsm_x4(uint32_t addr, uint32_t* r) {
    asm volatile("ldmatrix.sync.aligned.m8n8.x4.shared.b16 {%0,%1,%2,%3}, [%4];"
        : "=r"(r[0]), "=r"(r[1]), "=r"(r[2]), "=r"(r[3]) : "r"(addr));
}
__device__ __forceinline__ void mma16816(float* c, const uint32_t* a, const uint32_t* b) {
    asm volatile("mma.sync.aligned.m16n8k16.row.col.f32.f16.f16.f32 "
        "{%0,%1,%2,%3}, {%4,%5,%6,%7}, {%8,%9}, {%0,%1,%2,%3};"
        : "+f"(c[0]), "+f"(c[1]), "+f"(c[2]), "+f"(c[3])
        : "r"(a[0]), "r"(a[1]), "r"(a[2]), "r"(a[3]), "r"(b[0]), "r"(b[1]));
}
__device__ __forceinline__ unsigned long long pack2(float lo, float hi) {
    unsigned long long r;
    asm("mov.b64 %0, {%1, %2};" : "=l"(r) : "f"(lo), "f"(hi));
    return r;
}
__device__ __forceinline__ void unpack2(unsigned long long v, float& lo, float& hi) {
    asm("mov.b64 {%0, %1}, %2;" : "=f"(lo), "=f"(hi) : "l"(v));
}
__device__ __forceinline__ void fma2(unsigned long long& c, unsigned long long a,
                                     unsigned long long b) {
    asm("fma.rn.f32x2 %0, %1, %2, %0;" : "+l"(c) : "l"(a), "l"(b));
}
__device__ __forceinline__ float2 h2pair(unsigned h, unsigned l) {
    float2 a = __half22float2(*reinterpret_cast<const __half2*>(&h));
    float2 b = __half22float2(*reinterpret_cast<const __half2*>(&l));
    return make_float2(a.x + b.x, a.y + b.y);
}
#define CP_ASYNC16(dst, src) \
    asm volatile("cp.async.cg.shared.global [%0], [%1], 16;" :: "r"(dst), "l"(src))
#define CP_COMMIT() asm volatile("cp.async.commit_group;" ::: "memory")
#define CP_WAIT1()  asm volatile("cp.async.wait_group 1;" ::: "memory")
#define CP_WAIT0()  asm volatile("cp.async.wait_group 0;" ::: "memory")

// ---------------------------------------------------------------------------
// Kernel 1: per-point features Yt/Ct (f32x2 packed fma), sq norms, fp16 hi/lo
// ---------------------------------------------------------------------------
__global__ __launch_bounds__(128) void k1_features(
    const float* __restrict__ x, const float* __restrict__ W,
    const float* __restrict__ bvec)
{
    __shared__ float W2s[64][32];
    __shared__ float Wds[64][32];
    __shared__ float bs[32];

    const int bb   = blockIdx.y;
    const int n0   = blockIdx.x * 128;
    const int half = blockIdx.z;
    const int tid  = threadIdx.x;

    for (int idx = tid; idx < 64 * 32; idx += 128) {
        int f = idx >> 5, o = idx & 31;
        int og = half * 32 + o;
        float w1 = W[og * 128 + f];
        float w2 = W[og * 128 + 64 + f];
        W2s[f][o] = w2;
        Wds[f][o] = w1 - w2;
    }
    if (tid < 32) bs[tid] = bvec[half * 32 + tid];
    __syncthreads();

    const float* xb = x + (size_t)bb * FIN * NPTS;
    const int n = n0 + tid;

    float xr[64];
#pragma unroll
    for (int f = 0; f < 64; ++f) xr[f] = xb[f * NPTS + n];

    uint4* pdst = (uint4*)(g_p + ((size_t)(bb * NPTS + n)) * 128);
    if (half == 0) {
        float sq = 0.f;
#pragma unroll
        for (int f = 0; f < 64; ++f) sq = fmaf(xr[f], xr[f], sq);
        g_sq[bb * NPTS + n] = sq;
#pragma unroll
        for (int q = 0; q < 8; ++q) {
            __half2 h[4];
#pragma unroll
            for (int e = 0; e < 4; ++e)
                h[e] = __floats2half2_rn(xr[q * 8 + 2 * e], xr[q * 8 + 2 * e + 1]);
            pdst[q] = make_uint4(*(unsigned*)&h[0], *(unsigned*)&h[1],
                                 *(unsigned*)&h[2], *(unsigned*)&h[3]);
        }
    } else {
#pragma unroll
        for (int q = 0; q < 8; ++q) {
            float r[8];
#pragma unroll
            for (int e = 0; e < 8; ++e) {
                float xf = xr[q * 8 + e];
                r[e] = xf - __half2float(__float2half_rn(xf));
            }
            __half2 h[4];
#pragma unroll
            for (int e = 0; e < 4; ++e)
                h[e] = __floats2half2_rn(r[2 * e], r[2 * e + 1]);
            pdst[8 + q] = make_uint4(*(unsigned*)&h[0], *(unsigned*)&h[1],
                                     *(unsigned*)&h[2], *(unsigned*)&h[3]);
        }
    }

    const size_t base = ((size_t)(bb * NPTS + n)) * 64 + half * 32;

    unsigned long long ya2[16], ca2[16];
#pragma unroll
    for (int p = 0; p < 16; ++p) {
        ya2[p] = pack2(0.f, 0.f);
        ca2[p] = pack2(bs[2 * p], bs[2 * p + 1]);
    }

#pragma unroll 4
    for (int f = 0; f < 64; ++f) {
        const unsigned long long a2 = pack2(xr[f], xr[f]);
#pragma unroll
        for (int oo = 0; oo < 32; oo += 4) {
            float4 w2 = *(const float4*)&W2s[f][oo];
            float4 wd = *(const float4*)&Wds[f][oo];
            fma2(ya2[oo / 2],     a2, pack2(w2.x, w2.y));
            fma2(ya2[oo / 2 + 1], a2, pack2(w2.z, w2.w));
            fma2(ca2[oo / 2],     a2, pack2(wd.x, wd.y));
            fma2(ca2[oo / 2 + 1], a2, pack2(wd.z, wd.w));
        }
    }
    float4* Yp = (float4*)(g_Yt + base);
    float4* Cp = (float4*)(g_Ct + base);
#pragma unroll
    for (int q = 0; q < 8; ++q) {
        float y0, y1, y2, y3, c0, c1, c2, c3;
        unpack2(ya2[2 * q], y0, y1);
        unpack2(ya2[2 * q + 1], y2, y3);
        unpack2(ca2[2 * q], c0, c1);
        unpack2(ca2[2 * q + 1], c2, c3);
        Yp[q] = make_float4(y0, y1, y2, y3);
        Cp[q] = make_float4(c0, c1, c2, c3);
    }
}

// ---------------------------------------------------------------------------
// Kernel 2: 1-pass fp16-hi HMMA distance GEMM + warp-coop top-28 (approx)
// grid 256 (8 batches x 32 row-blocks of 128), 256 threads, 8 warps (4x2)
// NO refinement here (hoisted to k2b) -> low register pressure, no spills.
// ---------------------------------------------------------------------------
#define TNC 64                       // candidate cols per tile
#define NT  (NPTS / TNC)             // 64 tiles
#define DSS 66                       // Ds row stride (floats)

// smem byte offsets
#define SM_A   0                     // Ah[128][64] = 16KB
#define SM_B   16384                 // 2 bufs x 8KB (hi only)
#define SM_SQ  32768                 // 2 bufs x 64 floats = 512B
#define SM_D   33280                 // Ds 128 x 66 floats = 33792B
#define SM_TOT (SM_D + 128 * DSS * 4)   // 67072

__global__ __launch_bounds__(256, 2) void k2_knn(void)
{
    extern __shared__ char sm[];
    const uint32_t smem_base = smem_u32(sm);
    float* Ds = (float*)(sm + SM_D);

    const int tid  = threadIdx.x;
    const int wid  = tid >> 5;
    const int lane = tid & 31;
    const int wr   = wid & 3;        // warp row group (32 rows)
    const int wc   = wid >> 2;       // warp col group (32 cols)

    const int bb = blockIdx.x >> 5;
    const int n0 = (blockIdx.x & 31) * 128;

    const __half* gp = g_p + (size_t)bb * NPTS * 128;

    // ---- load A panel (hi only) swizzled: 128 rows x 8 chunks of 16B ----
    for (int idx = tid; idx < 1024; idx += 256) {
        int r = idx >> 3, ch = idx & 7;
        uint4 v = *(const uint4*)(gp + (size_t)(n0 + r) * 128 + ch * 8);
        *(uint4*)(sm + SM_A + r * 128 + ((ch ^ (r & 7)) << 4)) = v;
    }

    // ---- B tile loader (hi only, cp.async) ----
    auto loadB = [&](int t, int buf) {
        const __half* src0 = gp + (size_t)t * TNC * 128;
        uint32_t dst0 = smem_base + SM_B + buf * 8192;
#pragma unroll
        for (int k = 0; k < 2; ++k) {
            int idx = tid + k * 256;             // 0..511
            int r = idx >> 3, ch = idx & 7;
            CP_ASYNC16(dst0 + r * 128 + ((ch ^ (r & 7)) << 4),
                       src0 + (size_t)r * 128 + ch * 8);
        }
        if (tid < 16)
            CP_ASYNC16(smem_base + SM_SQ + buf * 256 + tid * 16,
                       g_sq + bb * NPTS + t * TNC + tid * 4);
    };

    // ---- selection state: warp owns 16 rows; top-28 across lanes 0..27 ----
    float lv[16];
    int   li[16];
#pragma unroll
    for (int r = 0; r < 16; ++r) { lv[r] = BIGF; li[r] = 0; }
    const int srow0 = wid * 16;

    loadB(0, 0);
    CP_COMMIT();

#pragma unroll 1
    for (int t = 0; t < NT; ++t) {
        const int cur = t & 1;
        if (t + 1 < NT) { loadB(t + 1, (t + 1) & 1); CP_COMMIT(); CP_WAIT1(); }
        else            { CP_WAIT0(); }
        __syncthreads();                 // tile t resident (and A on t==0)

        // ---- GEMM: single hi-pass, 4 k16 steps ----
        float acc[2][4][4];
#pragma unroll
        for (int mt = 0; mt < 2; ++mt)
#pragma unroll
            for (int nt = 0; nt < 4; ++nt)
#pragma unroll
                for (int e = 0; e < 4; ++e) acc[mt][nt][e] = 0.f;

        const uint32_t abase = smem_base + SM_A;
        const uint32_t bbase = smem_base + SM_B + cur * 8192;
#pragma unroll
        for (int ks = 0; ks < 4; ++ks) {
            uint32_t ah[2][4], bh[2][4];
            const int acha = ks * 2 + (lane >> 4);
            const int bcha = ks * 2 + ((lane >> 3) & 1);
#pragma unroll
            for (int mt = 0; mt < 2; ++mt) {
                int row = wr * 32 + mt * 16 + (lane & 15);
                ldsm_x4(abase + row * 128 + ((acha ^ (row & 7)) << 4), ah[mt]);
            }
#pragma unroll
            for (int g = 0; g < 2; ++g) {
                int row = wc * 32 + g * 16 + (lane & 7) + ((lane >> 4) << 3);
                ldsm_x4(bbase + row * 128 + ((bcha ^ (row & 7)) << 4), bh[g]);
            }
#pragma unroll
            for (int mt = 0; mt < 2; ++mt)
#pragma unroll
                for (int nt = 0; nt < 4; ++nt)
                    mma16816(acc[mt][nt], ah[mt], &bh[nt >> 1][(nt & 1) * 2]);
        }

        // ---- stage dot tile to smem (stride 66) ----
#pragma unroll
        for (int mt = 0; mt < 2; ++mt) {
            int row0 = wr * 32 + mt * 16 + (lane >> 2);
#pragma unroll
            for (int nt = 0; nt < 4; ++nt) {
                int col0 = wc * 32 + nt * 8 + 2 * (lane & 3);
                Ds[row0 * DSS + col0]           = acc[mt][nt][0];
                Ds[row0 * DSS + col0 + 1]       = acc[mt][nt][1];
                Ds[(row0 + 8) * DSS + col0]     = acc[mt][nt][2];
                Ds[(row0 + 8) * DSS + col0 + 1] = acc[mt][nt][3];
            }
        }
        __syncthreads();

        // ---- warp-cooperative top-28 (approx keys) ----
        const float2 sqv = ((const float2*)(sm + SM_SQ + cur * 256))[lane];
        const int m0g = t * TNC + 2 * lane;
        const int m1g = m0g + 1;

#pragma unroll
        for (int r = 0; r < 16; ++r) {
            const int row   = srow0 + r;
            const int nrowr = n0 + row;
            const float2 d2 = *(const float2*)&Ds[row * DSS + 2 * lane];
            float k0 = fmaf(-2.0f, d2.x, sqv.x);
            float k1 = fmaf(-2.0f, d2.y, sqv.y);
            if (m0g == nrowr) k0 = BIGF;          // self-exclusion
            if (m1g == nrowr) k1 = BIGF;

            float w = __shfl_sync(FULLMASK, lv[r], KSEL - 1);
            unsigned b = __ballot_sync(FULLMASK, fminf(k0, k1) < w);
            while (b) {
                const int s = __ffs(b) - 1;
                b &= b - 1;
                const float K0 = __shfl_sync(FULLMASK, k0, s);
                const float K1 = __shfl_sync(FULLMASK, k1, s);
                const int   mb = t * TNC + 2 * s;
#pragma unroll
                for (int e = 0; e < 2; ++e) {
                    const float key = e ? K1 : K0;
                    if (key < w) {
                        const float vprev = __shfl_up_sync(FULLMASK, lv[r], 1);
                        const int   iprev = __shfl_up_sync(FULLMASK, li[r], 1);
                        const bool pv    = lv[r] > key;
                        const bool pprev = (lane == 0) ? false : (vprev > key);
                        lv[r] = pv ? (pprev ? vprev : key) : lv[r];
                        li[r] = pv ? (pprev ? iprev : (mb + e)) : li[r];
                        w = __shfl_sync(FULLMASK, lv[r], KSEL - 1);
                    }
                }
            }
        }
        __syncthreads();                 // Ds / sq reusable
    }

    // ---- write the 28 survivors per row ----
#pragma unroll
    for (int r = 0; r < 16; ++r) {
        if (lane < KSEL)
            g_sel[((size_t)(bb * NPTS + n0 + srow0 + r)) * KSEL + lane] = li[r];
    }
}

// ---------------------------------------------------------------------------
// Kernel 2b: exact refinement — one warp per row, 28 -> exact top-20
// grid 4096, 256 threads (8 warps = 8 rows per CTA)
// ---------------------------------------------------------------------------
__global__ __launch_bounds__(256) void k2b_refine(void)
{
    const int lane = threadIdx.x & 31;
    const int gw   = blockIdx.x * 8 + (threadIdx.x >> 5);   // global row id
    const int bb   = gw >> 12;
    const int row  = gw & 4095;

    const __half* gp  = g_p + (size_t)bb * NPTS * 128;
    const float*  sqg = g_sq + (size_t)bb * NPTS;

    int myidx = (lane < KSEL) ? g_sel[(size_t)gw * KSEL + lane] : 0;

    const unsigned* pn = (const unsigned*)(gp + (size_t)row * 128);
    const float2 an = h2pair(pn[lane], pn[32 + lane]);

    float mykey = BIGF;
#pragma unroll 1
    for (int c = 0; c < KSEL; c += 2) {
        const int mA = __shfl_sync(FULLMASK, myidx, c);
        const int mB = __shfl_sync(FULLMASK, myidx, c + 1);
        const unsigned* pA = (const unsigned*)(gp + (size_t)mA * 128);
        const unsigned* pB = (const unsigned*)(gp + (size_t)mB * 128);
        const float2 aA = h2pair(pA[lane], pA[32 + lane]);
        const float2 aB = h2pair(pB[lane], pB[32 + lane]);
        float pa = fmaf(an.x, aA.x, an.y * aA.y);
        float pb = fmaf(an.x, aB.x, an.y * aB.y);
#pragma unroll
        for (int s = 16; s >= 1; s >>= 1) {
            pa += __shfl_xor_sync(FULLMASK, pa, s);
            pb += __shfl_xor_sync(FULLMASK, pb, s);
        }
        const float keyA = fmaf(-2.0f, pa, sqg[mA]);
        const float keyB = fmaf(-2.0f, pb, sqg[mB]);
        if (lane == c)     mykey = keyA;
        if (lane == c + 1) mykey = keyB;
    }

    // exact top-20 select from the 28 exact keys
    float nv = BIGF; int ni = 0;
    float w = BIGF;
#pragma unroll 1
    for (int s = 0; s < KSEL; ++s) {
        const float K = __shfl_sync(FULLMASK, mykey, s);
        const int   M = __shfl_sync(FULLMASK, myidx, s);
        if (K < w) {
            const float vprev = __shfl_up_sync(FULLMASK, nv, 1);
            const int   iprev = __shfl_up_sync(FULLMASK, ni, 1);
            const bool pv    = nv > K;
            const bool pprev = (lane == 0) ? false : (vprev > K);
            nv = pv ? (pprev ? vprev : K) : nv;
            ni = pv ? (pprev ? iprev : M) : ni;
            w = __shfl_sync(FULLMASK, nv, KNN - 1);
        }
    }
    if (lane < KNN)
        g_idx[(size_t)gw * KNN + lane] = ni;
}

// ---------------------------------------------------------------------------
// Kernel 3: gather-max epilogue + transpose to [b][o][n]
// ---------------------------------------------------------------------------
__global__ __launch_bounds__(256) void k3_epilogue(float* __restrict__ out)
{
    __shared__ float outs[64][65];
    const int bb  = blockIdx.y;
    const int n0  = blockIdx.x * 64;
    const int tid = threadIdx.x;
    const int w    = tid >> 5;
    const int lane = tid & 31;

    const float* Y = g_Yt + (size_t)bb * NPTS * 64;
    const float* C = g_Ct + (size_t)bb * NPTS * 64;

#pragma unroll 1
    for (int s = 0; s < 8; ++s) {
        int nn = w * 8 + s;
        int n  = n0 + nn;
        int jj = 0;
        if (lane < KNN) jj = g_idx[((size_t)(bb * NPTS + n)) * KNN + lane];
        float m0v = -3.0e38f, m1v = -3.0e38f;
#pragma unroll
        for (int i = 0; i < KNN; ++i) {
            int j = __shfl_sync(0xffffffffu, jj, i);
            const float* yr = Y + (size_t)j * 64;
            m0v = fmaxf(m0v, yr[lane]);
            m1v = fmaxf(m1v, yr[lane + 32]);
        }
        outs[nn][lane]      = m0v + C[(size_t)n * 64 + lane];
        outs[nn][lane + 32] = m1v + C[(size_t)n * 64 + lane + 32];
    }
    __syncthreads();

    float* ob = out + (size_t)bb * FOUT * NPTS;
#pragma unroll
    for (int it = 0; it < 16; ++it) {
        int lin = it * 256 + tid;
        int o  = lin >> 6;
        int nn = lin & 63;
        ob[o * NPTS + n0 + nn] = outs[nn][o];
    }
}

// ---------------------------------------------------------------------------
extern "C" void kernel_launch(void* const* d_in, const int* in_sizes, int n_in,
                              void* d_out, int out_size)
{
    const float* x    = (const float*)d_in[0];
    const float* W    = (const float*)d_in[1];
    const float* bvec = (const float*)d_in[2];
    float* out        = (float*)d_out;

    cudaFuncSetAttribute(k2_knn, cudaFuncAttributeMaxDynamicSharedMemorySize, SM_TOT);

    k1_features<<<dim3(NPTS / 128, BATCH, 2), 128>>>(x, W, bvec);
    k2_knn<<<BATCH * (NPTS / 128), 256, SM_TOT>>>();
    k2b_refine<<<BATCH * NPTS / 8, 256>>>();
    k3_epilogue<<<dim3(NPTS / 64, BATCH), 256>>>(out);
}

// round 10
// speedup vs baseline: 1.7909x; 1.1606x over previous
#include <cuda_runtime.h>
#include <cuda_fp16.h>
#include <cstdint>

// Problem constants
#define BATCH 8
#define FIN   64
#define NPTS  4096
#define FOUT  64
#define KNN   20
#define KSEL  24                     // stage-1 list size (slack over KNN)

#define FULLMASK 0xffffffffu
#define BIGF 3.0e38f

// ---------------------------------------------------------------------------
// Device scratch (no allocations allowed)
// ---------------------------------------------------------------------------
__device__ float g_Yt[BATCH * NPTS * FOUT];                    // W2 . x_n
__device__ float g_Ct[BATCH * NPTS * FOUT];                    // (W1-W2).x_n + b
__device__ __align__(16) float g_sq[BATCH * NPTS];             // ||x_n||^2
__device__ int   g_idx[BATCH * NPTS * KNN];                    // refined knn indices
__device__ int   g_sel[BATCH * NPTS * KSEL];                   // stage-1 candidates
__device__ __align__(16) __half g_p[BATCH * NPTS * 128];       // [hi(64)|lo(64)]

// ---------------------------------------------------------------------------
// Portable PTX helpers (compile fine for compute_103)
// ---------------------------------------------------------------------------
__device__ __forceinline__ uint32_t smem_u32(const void* p) {
    uint32_t a;
    asm("{ .reg .u64 t; cvta.to.shared.u64 t, %1; cvt.u32.u64 %0, t; }" : "=r"(a) : "l"(p));
    return a;
}
__device__ __forceinline__ void ldsm_x4(uint32_t addr, uint32_t* r) {
    asm volatile("ldmatrix.sync.aligned.m8n8.x4.shared.b16 {%0,%1,%2,%3}, [%4];"
        : "=r"(r[0]), "=r"(r[1]), "=r"(r[2]), "=r"(r[3]) : "r"(addr));
}
__device__ __forceinline__ void mma16816(float* c, const uint32_t* a, const uint32_t* b) {
    asm volatile("mma.sync.aligned.m16n8k16.row.col.f32.f16.f16.f32 "
        "{%0,%1,%2,%3}, {%4,%5,%6,%7}, {%8,%9}, {%0,%1,%2,%3};"
        : "+f"(c[0]), "+f"(c[1]), "+f"(c[2]), "+f"(c[3])
        : "r"(a[0]), "r"(a[1]), "r"(a[2]), "r"(a[3]), "r"(b[0]), "r"(b[1]));
}
__device__ __forceinline__ unsigned long long pack2(float lo, float hi) {
    unsigned long long r;
    asm("mov.b64 %0, {%1, %2};" : "=l"(r) : "f"(lo), "f"(hi));
    return r;
}
__device__ __forceinline__ void unpack2(unsigned long long v, float& lo, float& hi) {
    asm("mov.b64 {%0, %1}, %2;" : "=f"(lo), "=f"(hi) : "l"(v));
}
__device__ __forceinline__ void fma2(unsigned long long& c, unsigned long long a,
                                     unsigned long long b) {
    asm("fma.rn.f32x2 %0, %1, %2, %0;" : "+l"(c) : "l"(a), "l"(b));
}
__device__ __forceinline__ float2 h2pair(unsigned h, unsigned l) {
    float2 a = __half22float2(*reinterpret_cast<const __half2*>(&h));
    float2 b = __half22float2(*reinterpret_cast<const __half2*>(&l));
    return make_float2(a.x + b.x, a.y + b.y);
}
#define CP_ASYNC16(dst, src) \
    asm volatile("cp.async.cg.shared.global [%0], [%1], 16;" :: "r"(dst), "l"(src))
#define CP_COMMIT() asm volatile("cp.async.commit_group;" ::: "memory")
#define CP_WAIT0()  asm volatile("cp.async.wait_group 0;" ::: "memory")

// ---------------------------------------------------------------------------
// Kernel 1: per-point features Yt/Ct (f32x2 packed fma), sq norms, fp16 hi/lo
// ---------------------------------------------------------------------------
__global__ __launch_bounds__(128) void k1_features(
    const float* __restrict__ x, const float* __restrict__ W,
    const float* __restrict__ bvec)
{
    __shared__ float W2s[64][32];
    __shared__ float Wds[64][32];
    __shared__ float bs[32];

    const int bb   = blockIdx.y;
    const int n0   = blockIdx.x * 128;
    const int half = blockIdx.z;
    const int tid  = threadIdx.x;

    for (int idx = tid; idx < 64 * 32; idx += 128) {
        int f = idx >> 5, o = idx & 31;
        int og = half * 32 + o;
        float w1 = W[og * 128 + f];
        float w2 = W[og * 128 + 64 + f];
        W2s[f][o] = w2;
        Wds[f][o] = w1 - w2;
    }
    if (tid < 32) bs[tid] = bvec[half * 32 + tid];
    __syncthreads();

    const float* xb = x + (size_t)bb * FIN * NPTS;
    const int n = n0 + tid;

    float xr[64];
#pragma unroll
    for (int f = 0; f < 64; ++f) xr[f] = xb[f * NPTS + n];

    uint4* pdst = (uint4*)(g_p + ((size_t)(bb * NPTS + n)) * 128);
    if (half == 0) {
        float sq = 0.f;
#pragma unroll
        for (int f = 0; f < 64; ++f) sq = fmaf(xr[f], xr[f], sq);
        g_sq[bb * NPTS + n] = sq;
#pragma unroll
        for (int q = 0; q < 8; ++q) {
            __half2 h[4];
#pragma unroll
            for (int e = 0; e < 4; ++e)
                h[e] = __floats2half2_rn(xr[q * 8 + 2 * e], xr[q * 8 + 2 * e + 1]);
            pdst[q] = make_uint4(*(unsigned*)&h[0], *(unsigned*)&h[1],
                                 *(unsigned*)&h[2], *(unsigned*)&h[3]);
        }
    } else {
#pragma unroll
        for (int q = 0; q < 8; ++q) {
            float r[8];
#pragma unroll
            for (int e = 0; e < 8; ++e) {
                float xf = xr[q * 8 + e];
                r[e] = xf - __half2float(__float2half_rn(xf));
            }
            __half2 h[4];
#pragma unroll
            for (int e = 0; e < 4; ++e)
                h[e] = __floats2half2_rn(r[2 * e], r[2 * e + 1]);
            pdst[8 + q] = make_uint4(*(unsigned*)&h[0], *(unsigned*)&h[1],
                                     *(unsigned*)&h[2], *(unsigned*)&h[3]);
        }
    }

    const size_t base = ((size_t)(bb * NPTS + n)) * 64 + half * 32;

    unsigned long long ya2[16], ca2[16];
#pragma unroll
    for (int p = 0; p < 16; ++p) {
        ya2[p] = pack2(0.f, 0.f);
        ca2[p] = pack2(bs[2 * p], bs[2 * p + 1]);
    }

#pragma unroll 4
    for (int f = 0; f < 64; ++f) {
        const unsigned long long a2 = pack2(xr[f], xr[f]);
#pragma unroll
        for (int oo = 0; oo < 32; oo += 4) {
            float4 w2 = *(const float4*)&W2s[f][oo];
            float4 wd = *(const float4*)&Wds[f][oo];
            fma2(ya2[oo / 2],     a2, pack2(w2.x, w2.y));
            fma2(ya2[oo / 2 + 1], a2, pack2(w2.z, w2.w));
            fma2(ca2[oo / 2],     a2, pack2(wd.x, wd.y));
            fma2(ca2[oo / 2 + 1], a2, pack2(wd.z, wd.w));
        }
    }
    float4* Yp = (float4*)(g_Yt + base);
    float4* Cp = (float4*)(g_Ct + base);
#pragma unroll
    for (int q = 0; q < 8; ++q) {
        float y0, y1, y2, y3, c0, c1, c2, c3;
        unpack2(ya2[2 * q], y0, y1);
        unpack2(ya2[2 * q + 1], y2, y3);
        unpack2(ca2[2 * q], c0, c1);
        unpack2(ca2[2 * q + 1], c2, c3);
        Yp[q] = make_float4(y0, y1, y2, y3);
        Cp[q] = make_float4(c0, c1, c2, c3);
    }
}

// ---------------------------------------------------------------------------
// Kernel 2: 1-pass fp16-hi HMMA distance GEMM + warp-coop top-24 (approx)
// grid 256 (8 batches x 32 row-blocks of 128), 256 threads, 8 warps (4x2)
// Double-buffered Ds, ONE sync per tile, scan runs one tile behind GEMM.
// Inserts use a STALE threshold (sorted-insert is a no-op when beaten) -> no
// per-insert w-refresh shuffle: serial chain ~30 cyc instead of ~80.
// ---------------------------------------------------------------------------
#define TNC 64                       // candidate cols per tile
#define NT  (NPTS / TNC)             // 64 tiles
#define DSS 66                       // Ds row stride (floats)

// smem byte offsets
#define SM_A   0                     // Ah[128][64] = 16KB
#define SM_B   16384                 // 2 bufs x 8KB (hi only)
#define SM_D   32768                 // 2 bufs x (128 x 66 floats) = 67584B
#define SM_TOT (SM_D + 2 * 128 * DSS * 4)   // 100352

__global__ __launch_bounds__(256, 2) void k2_knn(void)
{
    extern __shared__ char sm[];
    const uint32_t smem_base = smem_u32(sm);
    float* Ds = (float*)(sm + SM_D);

    const int tid  = threadIdx.x;
    const int wid  = tid >> 5;
    const int lane = tid & 31;
    const int wr   = wid & 3;        // warp row group (32 rows)
    const int wc   = wid >> 2;       // warp col group (32 cols)

    const int bb = blockIdx.x >> 5;
    const int n0 = (blockIdx.x & 31) * 128;

    const __half* gp  = g_p + (size_t)bb * NPTS * 128;
    const float*  sqg = g_sq + (size_t)bb * NPTS;

    // ---- load A panel (hi only) swizzled: 128 rows x 8 chunks of 16B ----
    for (int idx = tid; idx < 1024; idx += 256) {
        int r = idx >> 3, ch = idx & 7;
        uint4 v = *(const uint4*)(gp + (size_t)(n0 + r) * 128 + ch * 8);
        *(uint4*)(sm + SM_A + r * 128 + ((ch ^ (r & 7)) << 4)) = v;
    }

    // ---- B tile loader (hi only, cp.async) ----
    auto loadB = [&](int t, int buf) {
        const __half* src0 = gp + (size_t)t * TNC * 128;
        uint32_t dst0 = smem_base + SM_B + buf * 8192;
#pragma unroll
        for (int k = 0; k < 2; ++k) {
            int idx = tid + k * 256;             // 0..511
            int r = idx >> 3, ch = idx & 7;
            CP_ASYNC16(dst0 + r * 128 + ((ch ^ (r & 7)) << 4),
                       src0 + (size_t)r * 128 + ch * 8);
        }
        CP_COMMIT();
    };

    // ---- selection state: warp owns 16 rows; top-24 across lanes 0..23 ----
    float lv[16];
    int   li[16];
#pragma unroll
    for (int r = 0; r < 16; ++r) { lv[r] = BIGF; li[r] = 0; }
    const int srow0 = wid * 16;

    // ---- scan of one tile (keys from Ds buffer tt&1, sq direct from L2) ----
    auto scanTile = [&](int tt) {
        const float* db = Ds + (tt & 1) * (128 * DSS);
        const float2 sqv = *(const float2*)(sqg + tt * TNC + 2 * lane);
        const int m0g = tt * TNC + 2 * lane;
        const int m1g = m0g + 1;
#pragma unroll
        for (int r = 0; r < 16; ++r) {
            const int row   = srow0 + r;
            const int nrowr = n0 + row;
            const float2 d2 = *(const float2*)&db[row * DSS + 2 * lane];
            float k0 = fmaf(-2.0f, d2.x, sqv.x);
            float k1 = fmaf(-2.0f, d2.y, sqv.y);
            if (m0g == nrowr) k0 = BIGF;          // self-exclusion
            if (m1g == nrowr) k1 = BIGF;

            const float w = __shfl_sync(FULLMASK, lv[r], KSEL - 1); // per-row-tile
            unsigned b = __ballot_sync(FULLMASK, fminf(k0, k1) < w);
            while (b) {
                const int s = __ffs(b) - 1;
                b &= b - 1;
                const float K0 = __shfl_sync(FULLMASK, k0, s);
                const float K1 = __shfl_sync(FULLMASK, k1, s);
                const int   mb = tt * TNC + 2 * s;
#pragma unroll
                for (int e = 0; e < 2; ++e) {
                    const float key = e ? K1 : K0;
                    // stale w guard: safe (sorted insert no-ops if beaten)
                    if (key < w) {
                        const float vprev = __shfl_up_sync(FULLMASK, lv[r], 1);
                        const int   iprev = __shfl_up_sync(FULLMASK, li[r], 1);
                        const bool pv    = lv[r] > key;
                        const bool pprev = (lane == 0) ? false : (vprev > key);
                        lv[r] = pv ? (pprev ? vprev : key) : lv[r];
                        li[r] = pv ? (pprev ? iprev : (mb + e)) : li[r];
                    }
                }
            }
        }
    };

    loadB(0, 0);

#pragma unroll 1
    for (int t = 0; t < NT; ++t) {
        CP_WAIT0();                      // B[t] landed (issued last iter)
        __syncthreads();                 // B visible; Ds[t&1] free; Ds[(t-1)&1] staged
        if (t + 1 < NT) loadB(t + 1, (t + 1) & 1);

        if (t > 0) scanTile(t - 1);      // consume previous tile's keys

        // ---- GEMM tile t: single hi-pass, 4 k16 steps ----
        float acc[2][4][4];
#pragma unroll
        for (int mt = 0; mt < 2; ++mt)
#pragma unroll
            for (int nt = 0; nt < 4; ++nt)
#pragma unroll
                for (int e = 0; e < 4; ++e) acc[mt][nt][e] = 0.f;

        const uint32_t abase = smem_base + SM_A;
        const uint32_t bbase = smem_base + SM_B + (t & 1) * 8192;
#pragma unroll
        for (int ks = 0; ks < 4; ++ks) {
            uint32_t ah[2][4], bh[2][4];
            const int acha = ks * 2 + (lane >> 4);
            const int bcha = ks * 2 + ((lane >> 3) & 1);
#pragma unroll
            for (int mt = 0; mt < 2; ++mt) {
                int row = wr * 32 + mt * 16 + (lane & 15);
                ldsm_x4(abase + row * 128 + ((acha ^ (row & 7)) << 4), ah[mt]);
            }
#pragma unroll
            for (int g = 0; g < 2; ++g) {
                int row = wc * 32 + g * 16 + (lane & 7) + ((lane >> 4) << 3);
                ldsm_x4(bbase + row * 128 + ((bcha ^ (row & 7)) << 4), bh[g]);
            }
#pragma unroll
            for (int mt = 0; mt < 2; ++mt)
#pragma unroll
                for (int nt = 0; nt < 4; ++nt)
                    mma16816(acc[mt][nt], ah[mt], &bh[nt >> 1][(nt & 1) * 2]);
        }

        // ---- stage dot tile into Ds[t&1] ----
        float* db = Ds + (t & 1) * (128 * DSS);
#pragma unroll
        for (int mt = 0; mt < 2; ++mt) {
            int row0 = wr * 32 + mt * 16 + (lane >> 2);
#pragma unroll
            for (int nt = 0; nt < 4; ++nt) {
                int col0 = wc * 32 + nt * 8 + 2 * (lane & 3);
                db[row0 * DSS + col0]           = acc[mt][nt][0];
                db[row0 * DSS + col0 + 1]       = acc[mt][nt][1];
                db[(row0 + 8) * DSS + col0]     = acc[mt][nt][2];
                db[(row0 + 8) * DSS + col0 + 1] = acc[mt][nt][3];
            }
        }
    }

    __syncthreads();                     // last tile staged
    scanTile(NT - 1);

    // ---- write the 24 survivors per row ----
#pragma unroll
    for (int r = 0; r < 16; ++r) {
        if (lane < KSEL)
            g_sel[((size_t)(bb * NPTS + n0 + srow0 + r)) * KSEL + lane] = li[r];
    }
}

// ---------------------------------------------------------------------------
// Kernel 2b: exact refinement — one warp per row, 24 -> exact top-20
// grid 4096, 256 threads (8 warps = 8 rows per CTA)
// ---------------------------------------------------------------------------
__global__ __launch_bounds__(256) void k2b_refine(void)
{
    const int lane = threadIdx.x & 31;
    const int gw   = blockIdx.x * 8 + (threadIdx.x >> 5);   // global row id
    const int bb   = gw >> 12;
    const int row  = gw & 4095;

    const __half* gp  = g_p + (size_t)bb * NPTS * 128;
    const float*  sqg = g_sq + (size_t)bb * NPTS;

    int myidx = (lane < KSEL) ? g_sel[(size_t)gw * KSEL + lane] : 0;

    const unsigned* pn = (const unsigned*)(gp + (size_t)row * 128);
    const float2 an = h2pair(pn[lane], pn[32 + lane]);

    float mykey = BIGF;
#pragma unroll 1
    for (int c = 0; c < KSEL; c += 2) {
        const int mA = __shfl_sync(FULLMASK, myidx, c);
        const int mB = __shfl_sync(FULLMASK, myidx, c + 1);
        const unsigned* pA = (const unsigned*)(gp + (size_t)mA * 128);
        const unsigned* pB = (const unsigned*)(gp + (size_t)mB * 128);
        const float2 aA = h2pair(pA[lane], pA[32 + lane]);
        const float2 aB = h2pair(pB[lane], pB[32 + lane]);
        float pa = fmaf(an.x, aA.x, an.y * aA.y);
        float pb = fmaf(an.x, aB.x, an.y * aB.y);
#pragma unroll
        for (int s = 16; s >= 1; s >>= 1) {
            pa += __shfl_xor_sync(FULLMASK, pa, s);
            pb += __shfl_xor_sync(FULLMASK, pb, s);
        }
        const float keyA = fmaf(-2.0f, pa, sqg[mA]);
        const float keyB = fmaf(-2.0f, pb, sqg[mB]);
        if (lane == c)     mykey = keyA;
        if (lane == c + 1) mykey = keyB;
    }

    // exact top-20 select from the 24 exact keys
    float nv = BIGF; int ni = 0;
    float w = BIGF;
#pragma unroll 1
    for (int s = 0; s < KSEL; ++s) {
        const float K = __shfl_sync(FULLMASK, mykey, s);
        const int   M = __shfl_sync(FULLMASK, myidx, s);
        if (K < w) {
            const float vprev = __shfl_up_sync(FULLMASK, nv, 1);
            const int   iprev = __shfl_up_sync(FULLMASK, ni, 1);
            const bool pv    = nv > K;
            const bool pprev = (lane == 0) ? false : (vprev > K);
            nv = pv ? (pprev ? vprev : K) : nv;
            ni = pv ? (pprev ? iprev : M) : ni;
            w = __shfl_sync(FULLMASK, nv, KNN - 1);
        }
    }
    if (lane < KNN)
        g_idx[(size_t)gw * KNN + lane] = ni;
}

// ---------------------------------------------------------------------------
// Kernel 3: gather-max epilogue + transpose to [b][o][n]
// ---------------------------------------------------------------------------
__global__ __launch_bounds__(256) void k3_epilogue(float* __restrict__ out)
{
    __shared__ float outs[64][65];
    const int bb  = blockIdx.y;
    const int n0  = blockIdx.x * 64;
    const int tid = threadIdx.x;
    const int w    = tid >> 5;
    const int lane = tid & 31;

    const float* Y = g_Yt + (size_t)bb * NPTS * 64;
    const float* C = g_Ct + (size_t)bb * NPTS * 64;

#pragma unroll 1
    for (int s = 0; s < 8; ++s) {
        int nn = w * 8 + s;
        int n  = n0 + nn;
        int jj = 0;
        if (lane < KNN) jj = g_idx[((size_t)(bb * NPTS + n)) * KNN + lane];
        float m0v = -3.0e38f, m1v = -3.0e38f;
#pragma unroll
        for (int i = 0; i < KNN; ++i) {
            int j = __shfl_sync(0xffffffffu, jj, i);
            const float* yr = Y + (size_t)j * 64;
            m0v = fmaxf(m0v, yr[lane]);
            m1v = fmaxf(m1v, yr[lane + 32]);
        }
        outs[nn][lane]      = m0v + C[(size_t)n * 64 + lane];
        outs[nn][lane + 32] = m1v + C[(size_t)n * 64 + lane + 32];
    }
    __syncthreads();

    float* ob = out + (size_t)bb * FOUT * NPTS;
#pragma unroll
    for (int it = 0; it < 16; ++it) {
        int lin = it * 256 + tid;
        int o  = lin >> 6;
        int nn = lin & 63;
        ob[o * NPTS + n0 + nn] = outs[nn][o];
    }
}

// ---------------------------------------------------------------------------
extern "C" void kernel_launch(void* const* d_in, const int* in_sizes, int n_in,
                              void* d_out, int out_size)
{
    const float* x    = (const float*)d_in[0];
    const float* W    = (const float*)d_in[1];
    const float* bvec = (const float*)d_in[2];
    float* out        = (float*)d_out;

    cudaFuncSetAttribute(k2_knn, cudaFuncAttributeMaxDynamicSharedMemorySize, SM_TOT);

    k1_features<<<dim3(NPTS / 128, BATCH, 2), 128>>>(x, W, bvec);
    k2_knn<<<BATCH * (NPTS / 128), 256, SM_TOT>>>();
    k2b_refine<<<BATCH * NPTS / 8, 256>>>();
    k3_epilogue<<<dim3(NPTS / 64, BATCH), 256>>>(out);
}

// round 11
// speedup vs baseline: 1.8352x; 1.0248x over previous
#include <cuda_runtime.h>
#include <cuda_fp16.h>
#include <cstdint>

// Problem constants
#define BATCH 8
#define FIN   64
#define NPTS  4096
#define FOUT  64
#define KNN   20
#define KSEL  24                     // stage-1 list size (slack over KNN)

#define FULLMASK 0xffffffffu
#define BIGF 3.0e38f

// ---------------------------------------------------------------------------
// Device scratch (no allocations allowed)
// ---------------------------------------------------------------------------
__device__ float g_Yt[BATCH * NPTS * FOUT];                    // W2 . x_n
__device__ float g_Ct[BATCH * NPTS * FOUT];                    // (W1-W2).x_n + b
__device__ __align__(16) float g_sq[BATCH * NPTS];             // ||x_n||^2
__device__ int   g_idx[BATCH * NPTS * KNN];                    // refined knn indices
__device__ int   g_sel[BATCH * NPTS * KSEL];                   // stage-1 candidates
__device__ __align__(16) __half g_p[BATCH * NPTS * 128];       // [hi(64)|lo(64)]

// ---------------------------------------------------------------------------
// Portable PTX helpers (compile fine for compute_103)
// ---------------------------------------------------------------------------
__device__ __forceinline__ uint32_t smem_u32(const void* p) {
    uint32_t a;
    asm("{ .reg .u64 t; cvta.to.shared.u64 t, %1; cvt.u32.u64 %0, t; }" : "=r"(a) : "l"(p));
    return a;
}
__device__ __forceinline__ void ldsm_x4(uint32_t addr, uint32_t* r) {
    asm volatile("ldmatrix.sync.aligned.m8n8.x4.shared.b16 {%0,%1,%2,%3}, [%4];"
        : "=r"(r[0]), "=r"(r[1]), "=r"(r[2]), "=r"(r[3]) : "r"(addr));
}
__device__ __forceinline__ void mma16816(float* c, const uint32_t* a, const uint32_t* b) {
    asm volatile("mma.sync.aligned.m16n8k16.row.col.f32.f16.f16.f32 "
        "{%0,%1,%2,%3}, {%4,%5,%6,%7}, {%8,%9}, {%0,%1,%2,%3};"
        : "+f"(c[0]), "+f"(c[1]), "+f"(c[2]), "+f"(c[3])
        : "r"(a[0]), "r"(a[1]), "r"(a[2]), "r"(a[3]), "r"(b[0]), "r"(b[1]));
}
__device__ __forceinline__ unsigned long long pack2(float lo, float hi) {
    unsigned long long r;
    asm("mov.b64 %0, {%1, %2};" : "=l"(r) : "f"(lo), "f"(hi));
    return r;
}
__device__ __forceinline__ void unpack2(unsigned long long v, float& lo, float& hi) {
    asm("mov.b64 {%0, %1}, %2;" : "=f"(lo), "=f"(hi) : "l"(v));
}
__device__ __forceinline__ void fma2(unsigned long long& c, unsigned long long a,
                                     unsigned long long b) {
    asm("fma.rn.f32x2 %0, %1, %2, %0;" : "+l"(c) : "l"(a), "l"(b));
}
__device__ __forceinline__ float2 h2pair(unsigned h, unsigned l) {
    float2 a = __half22float2(*reinterpret_cast<const __half2*>(&h));
    float2 b = __half22float2(*reinterpret_cast<const __half2*>(&l));
    return make_float2(a.x + b.x, a.y + b.y);
}
// ordered-int key packed with 12-bit candidate index in the low bits
__device__ __forceinline__ unsigned packkey(float k, int m) {
    unsigned u = __float_as_uint(k);
    u ^= (unsigned)((int)u >> 31) | 0x80000000u;
    return (u & 0xFFFFF000u) | (unsigned)m;
}
#define CP_ASYNC16(dst, src) \
    asm volatile("cp.async.cg.shared.global [%0], [%1], 16;" :: "r"(dst), "l"(src))
#define CP_COMMIT() asm volatile("cp.async.commit_group;" ::: "memory")
#define CP_WAIT0()  asm volatile("cp.async.wait_group 0;" ::: "memory")

// ---------------------------------------------------------------------------
// Kernel 1: per-point features Yt/Ct (f32x2 packed fma), sq norms, fp16 hi/lo
// ---------------------------------------------------------------------------
__global__ __launch_bounds__(128) void k1_features(
    const float* __restrict__ x, const float* __restrict__ W,
    const float* __restrict__ bvec)
{
    __shared__ float W2s[64][32];
    __shared__ float Wds[64][32];
    __shared__ float bs[32];

    const int bb   = blockIdx.y;
    const int n0   = blockIdx.x * 128;
    const int half = blockIdx.z;
    const int tid  = threadIdx.x;

    for (int idx = tid; idx < 64 * 32; idx += 128) {
        int f = idx >> 5, o = idx & 31;
        int og = half * 32 + o;
        float w1 = W[og * 128 + f];
        float w2 = W[og * 128 + 64 + f];
        W2s[f][o] = w2;
        Wds[f][o] = w1 - w2;
    }
    if (tid < 32) bs[tid] = bvec[half * 32 + tid];
    __syncthreads();

    const float* xb = x + (size_t)bb * FIN * NPTS;
    const int n = n0 + tid;

    float xr[64];
#pragma unroll
    for (int f = 0; f < 64; ++f) xr[f] = xb[f * NPTS + n];

    uint4* pdst = (uint4*)(g_p + ((size_t)(bb * NPTS + n)) * 128);
    if (half == 0) {
        float sq = 0.f;
#pragma unroll
        for (int f = 0; f < 64; ++f) sq = fmaf(xr[f], xr[f], sq);
        g_sq[bb * NPTS + n] = sq;
#pragma unroll
        for (int q = 0; q < 8; ++q) {
            __half2 h[4];
#pragma unroll
            for (int e = 0; e < 4; ++e)
                h[e] = __floats2half2_rn(xr[q * 8 + 2 * e], xr[q * 8 + 2 * e + 1]);
            pdst[q] = make_uint4(*(unsigned*)&h[0], *(unsigned*)&h[1],
                                 *(unsigned*)&h[2], *(unsigned*)&h[3]);
        }
    } else {
#pragma unroll
        for (int q = 0; q < 8; ++q) {
            float r[8];
#pragma unroll
            for (int e = 0; e < 8; ++e) {
                float xf = xr[q * 8 + e];
                r[e] = xf - __half2float(__float2half_rn(xf));
            }
            __half2 h[4];
#pragma unroll
            for (int e = 0; e < 4; ++e)
                h[e] = __floats2half2_rn(r[2 * e], r[2 * e + 1]);
            pdst[8 + q] = make_uint4(*(unsigned*)&h[0], *(unsigned*)&h[1],
                                     *(unsigned*)&h[2], *(unsigned*)&h[3]);
        }
    }

    const size_t base = ((size_t)(bb * NPTS + n)) * 64 + half * 32;

    unsigned long long ya2[16], ca2[16];
#pragma unroll
    for (int p = 0; p < 16; ++p) {
        ya2[p] = pack2(0.f, 0.f);
        ca2[p] = pack2(bs[2 * p], bs[2 * p + 1]);
    }

#pragma unroll 4
    for (int f = 0; f < 64; ++f) {
        const unsigned long long a2 = pack2(xr[f], xr[f]);
#pragma unroll
        for (int oo = 0; oo < 32; oo += 4) {
            float4 w2 = *(const float4*)&W2s[f][oo];
            float4 wd = *(const float4*)&Wds[f][oo];
            fma2(ya2[oo / 2],     a2, pack2(w2.x, w2.y));
            fma2(ya2[oo / 2 + 1], a2, pack2(w2.z, w2.w));
            fma2(ca2[oo / 2],     a2, pack2(wd.x, wd.y));
            fma2(ca2[oo / 2 + 1], a2, pack2(wd.z, wd.w));
        }
    }
    float4* Yp = (float4*)(g_Yt + base);
    float4* Cp = (float4*)(g_Ct + base);
#pragma unroll
    for (int q = 0; q < 8; ++q) {
        float y0, y1, y2, y3, c0, c1, c2, c3;
        unpack2(ya2[2 * q], y0, y1);
        unpack2(ya2[2 * q + 1], y2, y3);
        unpack2(ca2[2 * q], c0, c1);
        unpack2(ca2[2 * q + 1], c2, c3);
        Yp[q] = make_float4(y0, y1, y2, y3);
        Cp[q] = make_float4(c0, c1, c2, c3);
    }
}

// ---------------------------------------------------------------------------
// Kernel 2: 1-pass fp16-hi HMMA distance GEMM + warp-coop top-24 (approx)
// grid 256 (8 batches x 32 row-blocks of 128), 256 threads, 8 warps (4x2)
// Packed key+index lists (1 reg/slot, 1 shfl_up per insert). Scan of tile
// t-1 interleaved into the 4 ks GEMM steps of tile t (mma fills shfl gaps).
// ---------------------------------------------------------------------------
#define TNC 64                       // candidate cols per tile
#define NT  (NPTS / TNC)             // 64 tiles
#define DSS 66                       // Ds row stride (floats)

// smem byte offsets
#define SM_A   0                     // Ah[128][64] = 16KB
#define SM_B   16384                 // 2 bufs x 8KB (hi only)
#define SM_D   32768                 // 2 bufs x (128 x 66 floats) = 67584B
#define SM_TOT (SM_D + 2 * 128 * DSS * 4)   // 100352

__global__ __launch_bounds__(256, 2) void k2_knn(void)
{
    extern __shared__ char sm[];
    const uint32_t smem_base = smem_u32(sm);
    float* Ds = (float*)(sm + SM_D);

    const int tid  = threadIdx.x;
    const int wid  = tid >> 5;
    const int lane = tid & 31;
    const int wr   = wid & 3;        // warp row group (32 rows)
    const int wc   = wid >> 2;       // warp col group (32 cols)

    const int bb = blockIdx.x >> 5;
    const int n0 = (blockIdx.x & 31) * 128;

    const __half* gp  = g_p + (size_t)bb * NPTS * 128;
    const float*  sqg = g_sq + (size_t)bb * NPTS;

    // ---- load A panel (hi only) swizzled: 128 rows x 8 chunks of 16B ----
    for (int idx = tid; idx < 1024; idx += 256) {
        int r = idx >> 3, ch = idx & 7;
        uint4 v = *(const uint4*)(gp + (size_t)(n0 + r) * 128 + ch * 8);
        *(uint4*)(sm + SM_A + r * 128 + ((ch ^ (r & 7)) << 4)) = v;
    }

    // ---- B tile loader (hi only, cp.async) ----
    auto loadB = [&](int t, int buf) {
        const __half* src0 = gp + (size_t)t * TNC * 128;
        uint32_t dst0 = smem_base + SM_B + buf * 8192;
#pragma unroll
        for (int k = 0; k < 2; ++k) {
            int idx = tid + k * 256;             // 0..511
            int r = idx >> 3, ch = idx & 7;
            CP_ASYNC16(dst0 + r * 128 + ((ch ^ (r & 7)) << 4),
                       src0 + (size_t)r * 128 + ch * 8);
        }
        CP_COMMIT();
    };

    // ---- selection state: warp owns 16 rows; packed top-24, lanes 0..23 ----
    unsigned lv[16];
#pragma unroll
    for (int r = 0; r < 16; ++r) lv[r] = 0xFFFFFFFFu;
    const int srow0 = wid * 16;

    loadB(0, 0);

#pragma unroll 1
    for (int t = 0; t < NT; ++t) {
        CP_WAIT0();                      // B[t] landed (issued last iter)
        __syncthreads();                 // B visible; Ds[t&1] free; Ds[(t-1)&1] staged
        if (t + 1 < NT) loadB(t + 1, (t + 1) & 1);

        // per-(previous)-tile scan setup
        const int tp = t - 1;
        const float* dbp = Ds + (tp & 1) * (128 * DSS);
        float2 sqv = make_float2(0.f, 0.f);
        int m0g = 0;
        if (t > 0) {
            sqv = *(const float2*)(sqg + tp * TNC + 2 * lane);
            m0g = tp * TNC + 2 * lane;
        }

        float acc[2][4][4];
#pragma unroll
        for (int mt = 0; mt < 2; ++mt)
#pragma unroll
            for (int nt = 0; nt < 4; ++nt)
#pragma unroll
                for (int e = 0; e < 4; ++e) acc[mt][nt][e] = 0.f;

        const uint32_t abase = smem_base + SM_A;
        const uint32_t bbase = smem_base + SM_B + (t & 1) * 8192;

        // ---- interleaved: GEMM ks-step of tile t + 4-row scan of tile t-1 ----
#pragma unroll
        for (int ks = 0; ks < 4; ++ks) {
            // GEMM step
            uint32_t ah[2][4], bh[2][4];
            const int acha = ks * 2 + (lane >> 4);
            const int bcha = ks * 2 + ((lane >> 3) & 1);
#pragma unroll
            for (int mt = 0; mt < 2; ++mt) {
                int row = wr * 32 + mt * 16 + (lane & 15);
                ldsm_x4(abase + row * 128 + ((acha ^ (row & 7)) << 4), ah[mt]);
            }
#pragma unroll
            for (int g = 0; g < 2; ++g) {
                int row = wc * 32 + g * 16 + (lane & 7) + ((lane >> 4) << 3);
                ldsm_x4(bbase + row * 128 + ((bcha ^ (row & 7)) << 4), bh[g]);
            }
#pragma unroll
            for (int mt = 0; mt < 2; ++mt)
#pragma unroll
                for (int nt = 0; nt < 4; ++nt)
                    mma16816(acc[mt][nt], ah[mt], &bh[nt >> 1][(nt & 1) * 2]);

            // scan 4 rows of tile t-1
            if (t > 0) {
#pragma unroll
                for (int j = 0; j < 4; ++j) {
                    const int r = ks * 4 + j;           // compile-time constant
                    const int row   = srow0 + r;
                    const int nrowr = n0 + row;
                    const float2 d2 = *(const float2*)&dbp[row * DSS + 2 * lane];
                    const float k0 = fmaf(-2.0f, d2.x, sqv.x);
                    const float k1 = fmaf(-2.0f, d2.y, sqv.y);
                    const unsigned p0 = (m0g == nrowr)     ? 0xFFFFFFFFu
                                                           : packkey(k0, m0g);
                    const unsigned p1 = (m0g + 1 == nrowr) ? 0xFFFFFFFFu
                                                           : packkey(k1, m0g + 1);

                    const unsigned w = __shfl_sync(FULLMASK, lv[r], KSEL - 1);
                    unsigned b = __ballot_sync(FULLMASK, min(p0, p1) < w);
                    while (b) {
                        const int s = __ffs(b) - 1;
                        b &= b - 1;
                        const unsigned P0 = __shfl_sync(FULLMASK, p0, s);
                        const unsigned P1 = __shfl_sync(FULLMASK, p1, s);
#pragma unroll
                        for (int e = 0; e < 2; ++e) {
                            const unsigned P = e ? P1 : P0;
                            // stale w guard: safe (sorted insert no-ops if beaten)
                            if (P < w) {
                                const unsigned up = __shfl_up_sync(FULLMASK, lv[r], 1);
                                const bool pv    = lv[r] > P;
                                const bool pprev = (lane == 0) ? false : (up > P);
                                lv[r] = pv ? (pprev ? up : P) : lv[r];
                            }
                        }
                    }
                }
            }
        }

        // ---- stage dot tile into Ds[t&1] ----
        float* db = Ds + (t & 1) * (128 * DSS);
#pragma unroll
        for (int mt = 0; mt < 2; ++mt) {
            int row0 = wr * 32 + mt * 16 + (lane >> 2);
#pragma unroll
            for (int nt = 0; nt < 4; ++nt) {
                int col0 = wc * 32 + nt * 8 + 2 * (lane & 3);
                db[row0 * DSS + col0]           = acc[mt][nt][0];
                db[row0 * DSS + col0 + 1]       = acc[mt][nt][1];
                db[(row0 + 8) * DSS + col0]     = acc[mt][nt][2];
                db[(row0 + 8) * DSS + col0 + 1] = acc[mt][nt][3];
            }
        }
    }

    // ---- tail: scan the final tile ----
    __syncthreads();
    {
        const int tp = NT - 1;
        const float* dbp = Ds + (tp & 1) * (128 * DSS);
        const float2 sqv = *(const float2*)(sqg + tp * TNC + 2 * lane);
        const int m0g = tp * TNC + 2 * lane;
#pragma unroll
        for (int r = 0; r < 16; ++r) {
            const int row   = srow0 + r;
            const int nrowr = n0 + row;
            const float2 d2 = *(const float2*)&dbp[row * DSS + 2 * lane];
            const float k0 = fmaf(-2.0f, d2.x, sqv.x);
            const float k1 = fmaf(-2.0f, d2.y, sqv.y);
            const unsigned p0 = (m0g == nrowr)     ? 0xFFFFFFFFu : packkey(k0, m0g);
            const unsigned p1 = (m0g + 1 == nrowr) ? 0xFFFFFFFFu : packkey(k1, m0g + 1);

            const unsigned w = __shfl_sync(FULLMASK, lv[r], KSEL - 1);
            unsigned b = __ballot_sync(FULLMASK, min(p0, p1) < w);
            while (b) {
                const int s = __ffs(b) - 1;
                b &= b - 1;
                const unsigned P0 = __shfl_sync(FULLMASK, p0, s);
                const unsigned P1 = __shfl_sync(FULLMASK, p1, s);
#pragma unroll
                for (int e = 0; e < 2; ++e) {
                    const unsigned P = e ? P1 : P0;
                    if (P < w) {
                        const unsigned up = __shfl_up_sync(FULLMASK, lv[r], 1);
                        const bool pv    = lv[r] > P;
                        const bool pprev = (lane == 0) ? false : (up > P);
                        lv[r] = pv ? (pprev ? up : P) : lv[r];
                    }
                }
            }
        }
    }

    // ---- write the 24 survivors per row (index = low 12 bits) ----
#pragma unroll
    for (int r = 0; r < 16; ++r) {
        if (lane < KSEL)
            g_sel[((size_t)(bb * NPTS + n0 + srow0 + r)) * KSEL + lane]
                = (int)(lv[r] & 0xFFFu);
    }
}

// ---------------------------------------------------------------------------
// Kernel 2b: exact refinement — one warp per row, 24 -> exact top-20
// grid 4096, 256 threads (8 warps = 8 rows per CTA)
// ---------------------------------------------------------------------------
__global__ __launch_bounds__(256) void k2b_refine(void)
{
    const int lane = threadIdx.x & 31;
    const int gw   = blockIdx.x * 8 + (threadIdx.x >> 5);   // global row id
    const int bb   = gw >> 12;
    const int row  = gw & 4095;

    const __half* gp  = g_p + (size_t)bb * NPTS * 128;
    const float*  sqg = g_sq + (size_t)bb * NPTS;

    int myidx = (lane < KSEL) ? g_sel[(size_t)gw * KSEL + lane] : 0;

    const unsigned* pn = (const unsigned*)(gp + (size_t)row * 128);
    const float2 an = h2pair(pn[lane], pn[32 + lane]);

    float mykey = BIGF;
#pragma unroll 1
    for (int c = 0; c < KSEL; c += 2) {
        const int mA = __shfl_sync(FULLMASK, myidx, c);
        const int mB = __shfl_sync(FULLMASK, myidx, c + 1);
        const unsigned* pA = (const unsigned*)(gp + (size_t)mA * 128);
        const unsigned* pB = (const unsigned*)(gp + (size_t)mB * 128);
        const float2 aA = h2pair(pA[lane], pA[32 + lane]);
        const float2 aB = h2pair(pB[lane], pB[32 + lane]);
        float pa = fmaf(an.x, aA.x, an.y * aA.y);
        float pb = fmaf(an.x, aB.x, an.y * aB.y);
#pragma unroll
        for (int s = 16; s >= 1; s >>= 1) {
            pa += __shfl_xor_sync(FULLMASK, pa, s);
            pb += __shfl_xor_sync(FULLMASK, pb, s);
        }
        const float keyA = fmaf(-2.0f, pa, sqg[mA]);
        const float keyB = fmaf(-2.0f, pb, sqg[mB]);
        if (lane == c)     mykey = keyA;
        if (lane == c + 1) mykey = keyB;
    }

    // exact top-20 select from the 24 exact keys
    float nv = BIGF; int ni = 0;
    float w = BIGF;
#pragma unroll 1
    for (int s = 0; s < KSEL; ++s) {
        const float K = __shfl_sync(FULLMASK, mykey, s);
        const int   M = __shfl_sync(FULLMASK, myidx, s);
        if (K < w) {
            const float vprev = __shfl_up_sync(FULLMASK, nv, 1);
            const int   iprev = __shfl_up_sync(FULLMASK, ni, 1);
            const bool pv    = nv > K;
            const bool pprev = (lane == 0) ? false : (vprev > K);
            nv = pv ? (pprev ? vprev : K) : nv;
            ni = pv ? (pprev ? iprev : M) : ni;
            w = __shfl_sync(FULLMASK, nv, KNN - 1);
        }
    }
    if (lane < KNN)
        g_idx[(size_t)gw * KNN + lane] = ni;
}

// ---------------------------------------------------------------------------
// Kernel 3: gather-max epilogue + transpose to [b][o][n]
// ---------------------------------------------------------------------------
__global__ __launch_bounds__(256) void k3_epilogue(float* __restrict__ out)
{
    __shared__ float outs[64][65];
    const int bb  = blockIdx.y;
    const int n0  = blockIdx.x * 64;
    const int tid = threadIdx.x;
    const int w    = tid >> 5;
    const int lane = tid & 31;

    const float* Y = g_Yt + (size_t)bb * NPTS * 64;
    const float* C = g_Ct + (size_t)bb * NPTS * 64;

#pragma unroll 1
    for (int s = 0; s < 8; ++s) {
        int nn = w * 8 + s;
        int n  = n0 + nn;
        int jj = 0;
        if (lane < KNN) jj = g_idx[((size_t)(bb * NPTS + n)) * KNN + lane];
        float m0v = -3.0e38f, m1v = -3.0e38f;
#pragma unroll
        for (int i = 0; i < KNN; ++i) {
            int j = __shfl_sync(0xffffffffu, jj, i);
            const float* yr = Y + (size_t)j * 64;
            m0v = fmaxf(m0v, yr[lane]);
            m1v = fmaxf(m1v, yr[lane + 32]);
        }
        outs[nn][lane]      = m0v + C[(size_t)n * 64 + lane];
        outs[nn][lane + 32] = m1v + C[(size_t)n * 64 + lane + 32];
    }
    __syncthreads();

    float* ob = out + (size_t)bb * FOUT * NPTS;
#pragma unroll
    for (int it = 0; it < 16; ++it) {
        int lin = it * 256 + tid;
        int o  = lin >> 6;
        int nn = lin & 63;
        ob[o * NPTS + n0 + nn] = outs[nn][o];
    }
}

// ---------------------------------------------------------------------------
extern "C" void kernel_launch(void* const* d_in, const int* in_sizes, int n_in,
                              void* d_out, int out_size)
{
    const float* x    = (const float*)d_in[0];
    const float* W    = (const float*)d_in[1];
    const float* bvec = (const float*)d_in[2];
    float* out        = (float*)d_out;

    cudaFuncSetAttribute(k2_knn, cudaFuncAttributeMaxDynamicSharedMemorySize, SM_TOT);

    k1_features<<<dim3(NPTS / 128, BATCH, 2), 128>>>(x, W, bvec);
    k2_knn<<<BATCH * (NPTS / 128), 256, SM_TOT>>>();
    k2b_refine<<<BATCH * NPTS / 8, 256>>>();
    k3_epilogue<<<dim3(NPTS / 64, BATCH), 256>>>(out);
}